// round 11
// baseline (speedup 1.0000x reference)
#include <cuda_runtime.h>
#include <cuda_bf16.h>
#include <cstdint>

#define NTOK 4096   // B*L
#define DM   1024
#define DFF  4096
#define SEQ  2048

// ---------------- scratch (device globals: allocation-free) ----------------
__device__ float g_t0[NTOK * DM];
__device__ float g_t0b[NTOK * DM];
__device__ float g_x1[NTOK * DM];

__device__ __nv_bfloat16 g_xh[NTOK * DM],  g_xl[NTOK * DM];
__device__ __nv_bfloat16 g_qh[NTOK * DM],  g_ql[NTOK * DM];
__device__ __nv_bfloat16 g_kh[NTOK * DM],  g_kl[NTOK * DM];
__device__ __nv_bfloat16 g_vh[NTOK * DM],  g_vl[NTOK * DM];
__device__ __nv_bfloat16 g_ctxh[NTOK * DM], g_ctxl[NTOK * DM];
__device__ __nv_bfloat16 g_x1h[NTOK * DM], g_x1l[NTOK * DM];
__device__ __nv_bfloat16 g_ffh[(size_t)NTOK * DFF], g_ffl[(size_t)NTOK * DFF];
__device__ __nv_bfloat16 g_wqkvh[3 * DM * DM], g_wqkvl[3 * DM * DM];
__device__ float g_bqkv[3 * DM];
__device__ __nv_bfloat16 g_woh[DM * DM], g_wol[DM * DM];
__device__ __nv_bfloat16 g_w1h[(size_t)DFF * DM], g_w1l[(size_t)DFF * DM];
__device__ __nv_bfloat16 g_w2h[(size_t)DM * DFF], g_w2l[(size_t)DM * DFF];

// ---------------- PTX helpers (family-portable; NO tcgen05) ----------------
__device__ __forceinline__ uint32_t smem_u32(const void* p) {
    uint32_t a;
    asm("{ .reg .u64 t; cvta.to.shared.u64 t, %1; cvt.u32.u64 %0, t; }" : "=r"(a) : "l"(p));
    return a;
}
__device__ __forceinline__ void cpasync16(uint32_t dst, const void* src) {
    asm volatile("cp.async.cg.shared.global [%0], [%1], 16;" :: "r"(dst), "l"(src));
}
__device__ __forceinline__ void ldsm4(uint32_t (&r)[4], uint32_t addr) {
    asm volatile("ldmatrix.sync.aligned.m8n8.x4.shared.b16 {%0,%1,%2,%3}, [%4];"
        : "=r"(r[0]), "=r"(r[1]), "=r"(r[2]), "=r"(r[3]) : "r"(addr));
}
__device__ __forceinline__ void ldsm4t(uint32_t (&r)[4], uint32_t addr) {
    asm volatile("ldmatrix.sync.aligned.m8n8.x4.trans.shared.b16 {%0,%1,%2,%3}, [%4];"
        : "=r"(r[0]), "=r"(r[1]), "=r"(r[2]), "=r"(r[3]) : "r"(addr));
}
__device__ __forceinline__ void mma16816(float (&c)[4], const uint32_t (&a)[4],
                                         uint32_t b0, uint32_t b1) {
    asm volatile("mma.sync.aligned.m16n8k16.row.col.f32.bf16.bf16.f32 "
        "{%0,%1,%2,%3}, {%4,%5,%6,%7}, {%8,%9}, {%0,%1,%2,%3};"
        : "+f"(c[0]), "+f"(c[1]), "+f"(c[2]), "+f"(c[3])
        : "r"(a[0]), "r"(a[1]), "r"(a[2]), "r"(a[3]), "r"(b0), "r"(b1));
}
__device__ __forceinline__ uint32_t b2u(__nv_bfloat162 v) {
    return *reinterpret_cast<uint32_t*>(&v);
}
__device__ __forceinline__ void split_pack2(float a, float b, uint32_t& h, uint32_t& l) {
    __nv_bfloat162 hh = __floats2bfloat162_rn(a, b);
    h = b2u(hh);
    float ra = a - __bfloat162float(hh.x);
    float rb = b - __bfloat162float(hh.y);
    __nv_bfloat162 ll = __floats2bfloat162_rn(ra, rb);
    l = b2u(ll);
}
__device__ __forceinline__ uint32_t swz128(uint32_t off) { return off ^ ((off >> 3) & 0x70); }

// =====================================================================
// mma_gemm: C = (Ah+Al)[M,K] @ (Bh+Bl)[N,K]^T + bias
// epi: 0=none, 1=GELU. fused!=0: N=3072 QKV routing.
// kdiv: 1 or 2 (split-K via blockIdx.z; z=1 writes Cf2, bias only on z=0).
// 128x128 CTA tile, BK=64, 3-stage cp.async, 8 warps. MMAs issued in 3
// independent passes (hh, hl, lh) to break accumulator RAW chains.
// =====================================================================
#define GTILEB 16384
#define GSTAGEB (4 * GTILEB)
#define SMEM_MMA (3 * GSTAGEB + 1024)

__global__ __launch_bounds__(256, 1)
void mma_gemm(const __nv_bfloat16* __restrict__ Ah, const __nv_bfloat16* __restrict__ Al,
              const __nv_bfloat16* __restrict__ Bh, const __nv_bfloat16* __restrict__ Bl,
              const float* __restrict__ bias,
              float* __restrict__ Cf, float* __restrict__ Cf2,
              __nv_bfloat16* __restrict__ Ch0, __nv_bfloat16* __restrict__ Cl0,
              __nv_bfloat16* __restrict__ Ch1, __nv_bfloat16* __restrict__ Cl1,
              __nv_bfloat16* __restrict__ Ch2, __nv_bfloat16* __restrict__ Cl2,
              int M, int N, int K, int outN, int epi, int fused, int kdiv)
{
    extern __shared__ char smem[];
    const uint32_t s0 = (smem_u32(smem) + 1023) & ~1023u;

    const int tid = threadIdx.x;
    const int wid = tid >> 5, lid = tid & 31;
    const int brow = blockIdx.y << 7, bcol = blockIdx.x << 7;
    const int z = blockIdx.z;
    const int Kl_ = K / kdiv;           // K range handled by this z-slice
    const int kofs = z * Kl_;
    const int mw = (wid & 3) << 5;
    const int nw = (wid >> 2) << 6;

    const int lrow  = tid >> 1;
    const int lhalf = tid & 1;
    uint32_t sw[4];
#pragma unroll
    for (int i = 0; i < 4; i++)
        sw[i] = swz128(lrow * 128 + lhalf * 64 + i * 16);
    const size_t ga = (size_t)(brow + lrow) * K + kofs + lhalf * 32;
    const size_t gb = (size_t)(bcol + lrow) * K + kofs + lhalf * 32;

    const int nchunk = Kl_ >> 6;

    auto issue = [&](int c) {
        const uint32_t st = s0 + (uint32_t)(c % 3) * GSTAGEB;
        const size_t k0 = (size_t)c << 6;
#pragma unroll
        for (int i = 0; i < 4; i++) {
            cpasync16(st + 0 * GTILEB + sw[i], Ah + ga + k0 + i * 8);
            cpasync16(st + 1 * GTILEB + sw[i], Al + ga + k0 + i * 8);
            cpasync16(st + 2 * GTILEB + sw[i], Bh + gb + k0 + i * 8);
            cpasync16(st + 3 * GTILEB + sw[i], Bl + gb + k0 + i * 8);
        }
    };

    issue(0);
    asm volatile("cp.async.commit_group;");
    issue(1);
    asm volatile("cp.async.commit_group;");

    float acc[2][8][4];
#pragma unroll
    for (int i = 0; i < 2; i++)
#pragma unroll
        for (int j = 0; j < 8; j++)
#pragma unroll
            for (int t = 0; t < 4; t++) acc[i][j][t] = 0.f;

    const int a_row = lid & 15;
    const int a_h   = (lid >> 4) * 16;
    const int b_row = (lid & 7) + ((lid >> 4) << 3);
    const int b_h   = ((lid >> 3) & 1) * 16;

    for (int c = 0; c < nchunk; c++) {
        asm volatile("cp.async.wait_group 1;");
        __syncthreads();
        if (c + 2 < nchunk) issue(c + 2);
        asm volatile("cp.async.commit_group;");

        const uint32_t st  = s0 + (uint32_t)(c % 3) * GSTAGEB;
        const uint32_t sAh = st, sAl = st + GTILEB;
        const uint32_t sBh = st + 2 * GTILEB, sBl = st + 3 * GTILEB;

#pragma unroll
        for (int ks = 0; ks < 4; ks++) {
            uint32_t ah[2][4], al[2][4];
#pragma unroll
            for (int i = 0; i < 2; i++) {
                uint32_t off = swz128((mw + i * 16 + a_row) * 128 + ks * 32 + a_h);
                ldsm4(ah[i], sAh + off);
                ldsm4(al[i], sAl + off);
            }
            uint32_t bh[8][2], bl[8][2];
#pragma unroll
            for (int jj = 0; jj < 4; jj++) {
                uint32_t off = swz128((nw + jj * 16 + b_row) * 128 + ks * 32 + b_h);
                uint32_t t0[4], t1[4];
                ldsm4(t0, sBh + off);
                ldsm4(t1, sBl + off);
                bh[2*jj][0] = t0[0]; bh[2*jj][1] = t0[1]; bh[2*jj+1][0] = t0[2]; bh[2*jj+1][1] = t0[3];
                bl[2*jj][0] = t1[0]; bl[2*jj][1] = t1[1]; bl[2*jj+1][0] = t1[2]; bl[2*jj+1][1] = t1[3];
            }
            // pass 1: hi*hi — 16 independent MMAs
#pragma unroll
            for (int i = 0; i < 2; i++)
#pragma unroll
                for (int j = 0; j < 8; j++)
                    mma16816(acc[i][j], ah[i], bh[j][0], bh[j][1]);
            // pass 2: hi*lo
#pragma unroll
            for (int i = 0; i < 2; i++)
#pragma unroll
                for (int j = 0; j < 8; j++)
                    mma16816(acc[i][j], ah[i], bl[j][0], bl[j][1]);
            // pass 3: lo*hi
#pragma unroll
            for (int i = 0; i < 2; i++)
#pragma unroll
                for (int j = 0; j < 8; j++)
                    mma16816(acc[i][j], al[i], bh[j][0], bh[j][1]);
        }
    }

    // ---- epilogue ----
    int sel = fused ? (bcol >> 10) : 0;
    const int nbase = fused ? (bcol & 1023) : bcol;
    __nv_bfloat16* Ch = (sel == 0) ? Ch0 : (sel == 1) ? Ch1 : Ch2;
    __nv_bfloat16* Cl = (sel == 0) ? Cl0 : (sel == 1) ? Cl1 : Cl2;
    float* Cfd = (z == 0) ? Cf : Cf2;
    const bool addb = (z == 0);

    const int erow = lid >> 2;
    const int ecol = (lid & 3) << 1;
#pragma unroll
    for (int i = 0; i < 2; i++)
#pragma unroll
        for (int j = 0; j < 8; j++)
#pragma unroll
            for (int h = 0; h < 2; h++) {
                const int m = brow + mw + i * 16 + erow + h * 8;
                const int ng = bcol + nw + j * 8 + ecol;
                const int nl = nbase + nw + j * 8 + ecol;
                float v0 = acc[i][j][h * 2 + 0] + (addb ? bias[ng]     : 0.f);
                float v1 = acc[i][j][h * 2 + 1] + (addb ? bias[ng + 1] : 0.f);
                const size_t off = (size_t)m * outN + nl;
                if (epi == 1) {
                    v0 = 0.5f * v0 * (1.0f + erff(v0 * 0.70710678118654752f));
                    v1 = 0.5f * v1 * (1.0f + erff(v1 * 0.70710678118654752f));
                }
                if (Cfd) *(float2*)&Cfd[off] = make_float2(v0, v1);
                if (Ch) {
                    uint32_t hh, ll;
                    split_pack2(v0, v1, hh, ll);
                    *(uint32_t*)&Ch[off] = hh;
                    *(uint32_t*)&Cl[off] = ll;
                }
            }
}

// =====================================================================
// Causal flash attention via HMMA bf16 hi/lo split. fp32 softmax.
// =====================================================================
#define ATT_STAGEB 32768
#define SMEM_ATT (1024 + 32768 + 3 * ATT_STAGEB)

__global__ __launch_bounds__(256, 1)
void attn_mma(const __nv_bfloat16* __restrict__ Qh, const __nv_bfloat16* __restrict__ Ql,
              const __nv_bfloat16* __restrict__ Kh, const __nv_bfloat16* __restrict__ Kl,
              const __nv_bfloat16* __restrict__ Vh, const __nv_bfloat16* __restrict__ Vl,
              __nv_bfloat16* __restrict__ Oh, __nv_bfloat16* __restrict__ Ol)
{
    extern __shared__ char sm[];
    const uint32_t sQh = (smem_u32(sm) + 1023) & ~1023u;
    const uint32_t sQl = sQh + 16384;
    const uint32_t sKV = sQh + 32768;

    const int tid = threadIdx.x, wid = tid >> 5, lid = tid & 31;
    const int qt = (int)gridDim.x - 1 - (int)blockIdx.x;
    const int bh = blockIdx.y;
    const int b = bh >> 4, h = bh & 15;
    const int qbase = qt * 128;
    const size_t tok0 = (size_t)b * SEQ;
    const size_t hoff = (size_t)h * 64;
    const int mw = wid * 16;

    {
        const int r = tid >> 1;
        const int half = tid & 1;
        const size_t g = (tok0 + qbase + r) * DM + hoff + half * 32;
#pragma unroll
        for (int i = 0; i < 4; i++) {
            uint32_t so = swz128(r * 128 + half * 64 + i * 16);
            cpasync16(sQh + so, Qh + g + i * 8);
            cpasync16(sQl + so, Ql + g + i * 8);
        }
    }

    const int njt = 2 * qt + 2;
    const int kr = tid >> 2;
    const int kq = tid & 3;
    const uint32_t kso0 = swz128(kr * 128 + kq * 32);
    const uint32_t kso1 = swz128(kr * 128 + kq * 32 + 16);

    auto issue_kv = [&](int jt) {
        const uint32_t st = sKV + (uint32_t)(jt % 3) * ATT_STAGEB;
        const size_t g = (tok0 + jt * 64 + kr) * DM + hoff + kq * 16;
        cpasync16(st +         kso0, Kh + g);
        cpasync16(st +         kso1, Kh + g + 8);
        cpasync16(st +  8192 + kso0, Kl + g);
        cpasync16(st +  8192 + kso1, Kl + g + 8);
        cpasync16(st + 16384 + kso0, Vh + g);
        cpasync16(st + 16384 + kso1, Vh + g + 8);
        cpasync16(st + 24576 + kso0, Vl + g);
        cpasync16(st + 24576 + kso1, Vl + g + 8);
    };

    issue_kv(0);
    asm volatile("cp.async.commit_group;");
    issue_kv(1);
    asm volatile("cp.async.commit_group;");

    float O[8][4];
#pragma unroll
    for (int j = 0; j < 8; j++)
#pragma unroll
        for (int e = 0; e < 4; e++) O[j][e] = 0.f;
    float m0 = -1e30f, m1 = -1e30f, l0 = 0.f, l1 = 0.f;

    const int rql = lid >> 2;
    const int cql = (lid & 3) * 2;
    const int row0g = qbase + mw + rql;
    const int row1g = row0g + 8;

    for (int jt = 0; jt < njt; jt++) {
        asm volatile("cp.async.wait_group 1;");
        __syncthreads();
        if (jt + 2 < njt) issue_kv(jt + 2);
        asm volatile("cp.async.commit_group;");

        const bool active = !(mw < 64 && jt == njt - 1);
        if (active) {
            const uint32_t stKh = sKV + (uint32_t)(jt % 3) * ATT_STAGEB;
            const uint32_t stKl = stKh + 8192;
            const uint32_t stVh = stKh + 16384, stVl = stKh + 24576;

            float S[8][4];
#pragma unroll
            for (int j = 0; j < 8; j++)
#pragma unroll
                for (int e = 0; e < 4; e++) S[j][e] = 0.f;

#pragma unroll
            for (int ks = 0; ks < 4; ks++) {
                uint32_t qh4[4], ql4[4];
                uint32_t qoff = swz128((mw + (lid & 15)) * 128 + ks * 32 + (lid >> 4) * 16);
                ldsm4(qh4, sQh + qoff);
                ldsm4(ql4, sQl + qoff);
                uint32_t kfh[8][2], kfl[8][2];
#pragma unroll
                for (int jj = 0; jj < 4; jj++) {
                    uint32_t koff = swz128((jj * 16 + (lid & 7) + ((lid >> 4) << 3)) * 128
                                           + ks * 32 + ((lid >> 3) & 1) * 16);
                    uint32_t t0[4], t1[4];
                    ldsm4(t0, stKh + koff);
                    ldsm4(t1, stKl + koff);
                    kfh[2*jj][0]=t0[0]; kfh[2*jj][1]=t0[1]; kfh[2*jj+1][0]=t0[2]; kfh[2*jj+1][1]=t0[3];
                    kfl[2*jj][0]=t1[0]; kfl[2*jj][1]=t1[1]; kfl[2*jj+1][0]=t1[2]; kfl[2*jj+1][1]=t1[3];
                }
#pragma unroll
                for (int j = 0; j < 8; j++) mma16816(S[j], qh4, kfh[j][0], kfh[j][1]);
#pragma unroll
                for (int j = 0; j < 8; j++) mma16816(S[j], qh4, kfl[j][0], kfl[j][1]);
#pragma unroll
                for (int j = 0; j < 8; j++) mma16816(S[j], ql4, kfh[j][0], kfh[j][1]);
            }

            const int colb = jt * 64;
            const bool diag = (jt >= 2 * qt);
#pragma unroll
            for (int j = 0; j < 8; j++)
#pragma unroll
                for (int e = 0; e < 4; e++) {
                    float v = S[j][e] * 0.125f;
                    if (diag) {
                        int col = colb + 8 * j + cql + (e & 1);
                        int row = (e < 2) ? row0g : row1g;
                        if (col > row) v = -1e30f;
                    }
                    S[j][e] = v;
                }

            float rm0 = -1e30f, rm1 = -1e30f;
#pragma unroll
            for (int j = 0; j < 8; j++) {
                rm0 = fmaxf(rm0, fmaxf(S[j][0], S[j][1]));
                rm1 = fmaxf(rm1, fmaxf(S[j][2], S[j][3]));
            }
            rm0 = fmaxf(rm0, __shfl_xor_sync(0xffffffffu, rm0, 1));
            rm0 = fmaxf(rm0, __shfl_xor_sync(0xffffffffu, rm0, 2));
            rm1 = fmaxf(rm1, __shfl_xor_sync(0xffffffffu, rm1, 1));
            rm1 = fmaxf(rm1, __shfl_xor_sync(0xffffffffu, rm1, 2));
            float mn0 = fmaxf(m0, rm0), mn1 = fmaxf(m1, rm1);
            float a0 = __expf(m0 - mn0), a1 = __expf(m1 - mn1);
            m0 = mn0; m1 = mn1;
            float rs0 = 0.f, rs1 = 0.f;
#pragma unroll
            for (int j = 0; j < 8; j++) {
                S[j][0] = __expf(S[j][0] - mn0);
                S[j][1] = __expf(S[j][1] - mn0);
                S[j][2] = __expf(S[j][2] - mn1);
                S[j][3] = __expf(S[j][3] - mn1);
                rs0 += S[j][0] + S[j][1];
                rs1 += S[j][2] + S[j][3];
            }
            rs0 += __shfl_xor_sync(0xffffffffu, rs0, 1);
            rs0 += __shfl_xor_sync(0xffffffffu, rs0, 2);
            rs1 += __shfl_xor_sync(0xffffffffu, rs1, 1);
            rs1 += __shfl_xor_sync(0xffffffffu, rs1, 2);
            l0 = l0 * a0 + rs0;
            l1 = l1 * a1 + rs1;
#pragma unroll
            for (int j = 0; j < 8; j++) {
                O[j][0] *= a0; O[j][1] *= a0; O[j][2] *= a1; O[j][3] *= a1;
            }

            uint32_t pah[4][4], pal[4][4];
#pragma unroll
            for (int ks = 0; ks < 4; ks++) {
                split_pack2(S[2*ks][0],   S[2*ks][1],   pah[ks][0], pal[ks][0]);
                split_pack2(S[2*ks][2],   S[2*ks][3],   pah[ks][1], pal[ks][1]);
                split_pack2(S[2*ks+1][0], S[2*ks+1][1], pah[ks][2], pal[ks][2]);
                split_pack2(S[2*ks+1][2], S[2*ks+1][3], pah[ks][3], pal[ks][3]);
            }

#pragma unroll
            for (int ks = 0; ks < 4; ks++) {
                uint32_t vfh[8][2], vfl[8][2];
                const int rowv = ks * 16 + ((lid >> 3) & 1) * 8 + (lid & 7);
                const int colv = (lid >> 4) * 16;
#pragma unroll
                for (int nb = 0; nb < 4; nb++) {
                    uint32_t voff = swz128(rowv * 128 + nb * 32 + colv);
                    uint32_t t0[4], t1[4];
                    ldsm4t(t0, stVh + voff);
                    ldsm4t(t1, stVl + voff);
                    vfh[2*nb][0]=t0[0]; vfh[2*nb][1]=t0[1]; vfh[2*nb+1][0]=t0[2]; vfh[2*nb+1][1]=t0[3];
                    vfl[2*nb][0]=t1[0]; vfl[2*nb][1]=t1[1]; vfl[2*nb+1][0]=t1[2]; vfl[2*nb+1][1]=t1[3];
                }
#pragma unroll
                for (int j = 0; j < 8; j++) mma16816(O[j], pah[ks], vfh[j][0], vfh[j][1]);
#pragma unroll
                for (int j = 0; j < 8; j++) mma16816(O[j], pah[ks], vfl[j][0], vfl[j][1]);
#pragma unroll
                for (int j = 0; j < 8; j++) mma16816(O[j], pal[ks], vfh[j][0], vfh[j][1]);
            }
        }
    }

    const float inv0 = 1.0f / l0, inv1 = 1.0f / l1;
    const size_t tq0 = (tok0 + row0g) * DM + hoff;
    const size_t tq1 = (tok0 + row1g) * DM + hoff;
#pragma unroll
    for (int j = 0; j < 8; j++) {
        const int c = 8 * j + cql;
        uint32_t hh, ll;
        split_pack2(O[j][0] * inv0, O[j][1] * inv0, hh, ll);
        *(uint32_t*)&Oh[tq0 + c] = hh;
        *(uint32_t*)&Ol[tq0 + c] = ll;
        split_pack2(O[j][2] * inv1, O[j][3] * inv1, hh, ll);
        *(uint32_t*)&Oh[tq1 + c] = hh;
        *(uint32_t*)&Ol[tq1 + c] = ll;
    }
}

// =====================================================================
// conversions
// =====================================================================
__device__ __forceinline__ void split_bf16(float v, __nv_bfloat16& h, __nv_bfloat16& l) {
    h = __float2bfloat16(v);
    l = __float2bfloat16(v - __bfloat162float(h));
}

__global__ __launch_bounds__(256)
void conv_act(const float* __restrict__ in, __nv_bfloat16* __restrict__ hi,
              __nv_bfloat16* __restrict__ lo)
{
    const size_t i = ((size_t)blockIdx.x * 256 + threadIdx.x) * 4;
    float4 v = *(const float4*)(in + i);
    uint32_t h0, l0, h1, l1;
    split_pack2(v.x, v.y, h0, l0);
    split_pack2(v.z, v.w, h1, l1);
    *(uint32_t*)&hi[i]     = h0;
    *(uint32_t*)&hi[i + 2] = h1;
    *(uint32_t*)&lo[i]     = l0;
    *(uint32_t*)&lo[i + 2] = l1;
}

__global__ __launch_bounds__(256)
void conv_wT(const float* __restrict__ W, __nv_bfloat16* __restrict__ hi,
             __nv_bfloat16* __restrict__ lo, int K, int N)
{
    __shared__ float t[32][33];
    const int n0 = blockIdx.x * 32, k0 = blockIdx.y * 32;
    const int tx = threadIdx.x & 31, ty = threadIdx.x >> 5;
#pragma unroll
    for (int j = 0; j < 4; j++)
        t[ty + 8 * j][tx] = W[(size_t)(k0 + ty + 8 * j) * N + n0 + tx];
    __syncthreads();
#pragma unroll
    for (int j = 0; j < 4; j++) {
        float v = t[tx][ty + 8 * j];
        __nv_bfloat16 h, l;
        split_bf16(v, h, l);
        size_t o = (size_t)(n0 + ty + 8 * j) * K + k0 + tx;
        hi[o] = h; lo[o] = l;
    }
}

__global__ __launch_bounds__(256)
void conv_wT3(const float* __restrict__ W0, const float* __restrict__ W1,
              const float* __restrict__ W2, __nv_bfloat16* __restrict__ hi,
              __nv_bfloat16* __restrict__ lo)
{
    __shared__ float t[32][33];
    const int n0 = blockIdx.x * 32, k0 = blockIdx.y * 32;
    const int sel = n0 >> 10;
    const int nl = n0 & 1023;
    const float* W = (sel == 0) ? W0 : (sel == 1) ? W1 : W2;
    const int tx = threadIdx.x & 31, ty = threadIdx.x >> 5;
#pragma unroll
    for (int j = 0; j < 4; j++)
        t[ty + 8 * j][tx] = W[(size_t)(k0 + ty + 8 * j) * 1024 + nl + tx];
    __syncthreads();
#pragma unroll
    for (int j = 0; j < 4; j++) {
        float v = t[tx][ty + 8 * j];
        __nv_bfloat16 h, l;
        split_bf16(v, h, l);
        size_t o = (size_t)(n0 + ty + 8 * j) * 1024 + k0 + tx;
        hi[o] = h; lo[o] = l;
    }
}

__global__ void bias_cat(const float* __restrict__ b0, const float* __restrict__ b1,
                         const float* __restrict__ b2, float* __restrict__ out)
{
    int i = blockIdx.x * 256 + threadIdx.x;
    out[i] = (i < 1024) ? b0[i] : (i < 2048) ? b1[i - 1024] : b2[i - 2048];
}

// =====================================================================
// LayerNorm over (inA + inB? + res?) (+ optional bf16 hi/lo split out)
// =====================================================================
__global__ __launch_bounds__(256)
void ln_kernel(const float* __restrict__ inA, const float* __restrict__ inB,
               const float* __restrict__ res,
               const float* __restrict__ gamma, const float* __restrict__ beta,
               float* __restrict__ out,
               __nv_bfloat16* __restrict__ oh, __nv_bfloat16* __restrict__ ol)
{
    __shared__ float rs[8], rs2[8];
    const int row = blockIdx.x;
    const int t = threadIdx.x;
    float4 v = ((const float4*)(inA + (size_t)row * DM))[t];
    if (inB) {
        float4 b = ((const float4*)(inB + (size_t)row * DM))[t];
        v.x += b.x; v.y += b.y; v.z += b.z; v.w += b.w;
    }
    if (res) {
        float4 r = ((const float4*)(res + (size_t)row * DM))[t];
        v.x += r.x; v.y += r.y; v.z += r.z; v.w += r.w;
    }
    float s  = v.x + v.y + v.z + v.w;
    float s2 = v.x * v.x + v.y * v.y + v.z * v.z + v.w * v.w;
#pragma unroll
    for (int off = 16; off; off >>= 1) {
        s  += __shfl_xor_sync(0xffffffffu, s, off);
        s2 += __shfl_xor_sync(0xffffffffu, s2, off);
    }
    if ((t & 31) == 0) { rs[t >> 5] = s; rs2[t >> 5] = s2; }
    __syncthreads();
    float ts = 0.f, ts2 = 0.f;
#pragma unroll
    for (int w = 0; w < 8; w++) { ts += rs[w]; ts2 += rs2[w]; }
    float mu   = ts * (1.0f / DM);
    float var  = ts2 * (1.0f / DM) - mu * mu;
    float rstd = rsqrtf(var + 1e-5f);
    float4 g4 = ((const float4*)gamma)[t];
    float4 b4 = ((const float4*)beta)[t];
    float4 o4;
    o4.x = (v.x - mu) * rstd * g4.x + b4.x;
    o4.y = (v.y - mu) * rstd * g4.y + b4.y;
    o4.z = (v.z - mu) * rstd * g4.z + b4.z;
    o4.w = (v.w - mu) * rstd * g4.w + b4.w;
    if (out) ((float4*)(out + (size_t)row * DM))[t] = o4;
    if (oh) {
        const size_t i = (size_t)row * DM + t * 4;
        uint32_t h0, l0, h1, l1;
        split_pack2(o4.x, o4.y, h0, l0);
        split_pack2(o4.z, o4.w, h1, l1);
        *(uint32_t*)&oh[i]     = h0;
        *(uint32_t*)&oh[i + 2] = h1;
        *(uint32_t*)&ol[i]     = l0;
        *(uint32_t*)&ol[i + 2] = l1;
    }
}

// =====================================================================
extern "C" void kernel_launch(void* const* d_in, const int* in_sizes, int n_in,
                              void* d_out, int out_size)
{
    (void)in_sizes; (void)n_in; (void)out_size;
    const float* x   = (const float*)d_in[0];
    const float* Wq  = (const float*)d_in[1];
    const float* bq  = (const float*)d_in[2];
    const float* Wk  = (const float*)d_in[3];
    const float* bk  = (const float*)d_in[4];
    const float* Wv  = (const float*)d_in[5];
    const float* bv  = (const float*)d_in[6];
    const float* Wo  = (const float*)d_in[7];
    const float* bo  = (const float*)d_in[8];
    const float* W1  = (const float*)d_in[9];
    const float* b1  = (const float*)d_in[10];
    const float* W2  = (const float*)d_in[11];
    const float* b2  = (const float*)d_in[12];
    const float* g1  = (const float*)d_in[13];
    const float* be1 = (const float*)d_in[14];
    const float* g2  = (const float*)d_in[15];
    const float* be2 = (const float*)d_in[16];
    float* out = (float*)d_out;

    float *gt0, *gt0b, *gx1, *gbqkv;
    cudaGetSymbolAddress((void**)&gt0,  g_t0);
    cudaGetSymbolAddress((void**)&gt0b, g_t0b);
    cudaGetSymbolAddress((void**)&gx1,  g_x1);
    cudaGetSymbolAddress((void**)&gbqkv, g_bqkv);

    __nv_bfloat16 *xh, *xl, *qh, *ql, *kh, *kl, *vh, *vl, *ctxh, *ctxl, *x1h, *x1l, *ffh, *ffl;
    __nv_bfloat16 *wqkvh, *wqkvl, *woh, *wol, *w1h, *w1l, *w2h, *w2l;
    cudaGetSymbolAddress((void**)&xh,    g_xh);    cudaGetSymbolAddress((void**)&xl,    g_xl);
    cudaGetSymbolAddress((void**)&qh,    g_qh);    cudaGetSymbolAddress((void**)&ql,    g_ql);
    cudaGetSymbolAddress((void**)&kh,    g_kh);    cudaGetSymbolAddress((void**)&kl,    g_kl);
    cudaGetSymbolAddress((void**)&vh,    g_vh);    cudaGetSymbolAddress((void**)&vl,    g_vl);
    cudaGetSymbolAddress((void**)&ctxh,  g_ctxh);  cudaGetSymbolAddress((void**)&ctxl,  g_ctxl);
    cudaGetSymbolAddress((void**)&x1h,   g_x1h);   cudaGetSymbolAddress((void**)&x1l,   g_x1l);
    cudaGetSymbolAddress((void**)&ffh,   g_ffh);   cudaGetSymbolAddress((void**)&ffl,   g_ffl);
    cudaGetSymbolAddress((void**)&wqkvh, g_wqkvh); cudaGetSymbolAddress((void**)&wqkvl, g_wqkvl);
    cudaGetSymbolAddress((void**)&woh,   g_woh);   cudaGetSymbolAddress((void**)&wol,   g_wol);
    cudaGetSymbolAddress((void**)&w1h,   g_w1h);   cudaGetSymbolAddress((void**)&w1l,   g_w1l);
    cudaGetSymbolAddress((void**)&w2h,   g_w2h);   cudaGetSymbolAddress((void**)&w2l,   g_w2l);

    cudaFuncSetAttribute(mma_gemm, cudaFuncAttributeMaxDynamicSharedMemorySize, SMEM_MMA);
    cudaFuncSetAttribute(attn_mma, cudaFuncAttributeMaxDynamicSharedMemorySize, SMEM_ATT);

    // ---- weight prep ----
    conv_wT3<<<dim3(3 * DM / 32, DM / 32), 256>>>(Wq, Wk, Wv, wqkvh, wqkvl);
    conv_wT<<<dim3(DM / 32,  DM / 32),  256>>>(Wo, woh, wol, DM, DM);
    conv_wT<<<dim3(DFF / 32, DM / 32),  256>>>(W1, w1h, w1l, DM, DFF);
    conv_wT<<<dim3(DM / 32,  DFF / 32), 256>>>(W2, w2h, w2l, DFF, DM);
    bias_cat<<<12, 256>>>(bq, bk, bv, gbqkv);

    // ---- x split ----
    conv_act<<<(NTOK * DM) / 1024, 256>>>(x, xh, xl);

    // ---- fused QKV GEMM (N=3072) ----
    mma_gemm<<<dim3(3 * DM / 128, NTOK / 128, 1), 256, SMEM_MMA>>>(
        xh, xl, wqkvh, wqkvl, gbqkv, nullptr, nullptr,
        qh, ql, kh, kl, vh, vl, NTOK, 3 * DM, DM, DM, 0, 1, 1);

    // ---- attention ----
    attn_mma<<<dim3(SEQ / 128, 32), 256, SMEM_ATT>>>(qh, ql, kh, kl, vh, vl, ctxh, ctxl);

    // ---- Wo (split-K=2) -> partials; LN1 sums partials + x residual ----
    mma_gemm<<<dim3(DM / 128, NTOK / 128, 2), 256, SMEM_MMA>>>(
        ctxh, ctxl, woh, wol, bo, gt0, gt0b,
        nullptr, nullptr, nullptr, nullptr, nullptr, nullptr, NTOK, DM, DM, DM, 0, 0, 2);
    ln_kernel<<<NTOK, 256>>>(gt0, gt0b, x, g1, be1, gx1, x1h, x1l);

    // ---- FFN ----
    mma_gemm<<<dim3(DFF / 128, NTOK / 128, 1), 256, SMEM_MMA>>>(
        x1h, x1l, w1h, w1l, b1, nullptr, nullptr,
        ffh, ffl, nullptr, nullptr, nullptr, nullptr, NTOK, DFF, DM, DFF, 1, 0, 1);
    mma_gemm<<<dim3(DM / 128, NTOK / 128, 2), 256, SMEM_MMA>>>(
        ffh, ffl, w2h, w2l, b2, gt0, gt0b,
        nullptr, nullptr, nullptr, nullptr, nullptr, nullptr, NTOK, DM, DFF, DM, 0, 0, 2);
    ln_kernel<<<NTOK, 256>>>(gt0, gt0b, gx1, g2, be2, out, nullptr, nullptr);
}

// round 12
// speedup vs baseline: 1.3300x; 1.3300x over previous
#include <cuda_runtime.h>
#include <cuda_fp16.h>
#include <cstdint>

#define NTOK 4096   // B*L
#define DM   1024
#define DFF  4096
#define SEQ  2048

// ---------------- scratch (device globals: allocation-free) ----------------
__device__ float g_t0[NTOK * DM];
__device__ float g_x1[NTOK * DM];

__device__ __half g_xh[NTOK * DM],  g_xl[NTOK * DM];
__device__ __half g_qh[NTOK * DM],  g_ql[NTOK * DM];
__device__ __half g_kh[NTOK * DM],  g_kl[NTOK * DM];
__device__ __half g_vh[NTOK * DM],  g_vl[NTOK * DM];
__device__ __half g_ctxh[NTOK * DM], g_ctxl[NTOK * DM];
__device__ __half g_x1h[NTOK * DM], g_x1l[NTOK * DM];
__device__ __half g_ffh[(size_t)NTOK * DFF], g_ffl[(size_t)NTOK * DFF];
// single-precision-fp16 transposed weights [N,K]
__device__ __half g_wqkvh[3 * DM * DM];
__device__ float g_bqkv[3 * DM];
__device__ __half g_woh[DM * DM];
__device__ __half g_w1h[(size_t)DFF * DM];
__device__ __half g_w2h[(size_t)DM * DFF];

// ---------------- PTX helpers (family-portable; NO tcgen05) ----------------
__device__ __forceinline__ uint32_t smem_u32(const void* p) {
    uint32_t a;
    asm("{ .reg .u64 t; cvta.to.shared.u64 t, %1; cvt.u32.u64 %0, t; }" : "=r"(a) : "l"(p));
    return a;
}
__device__ __forceinline__ void cpasync16(uint32_t dst, const void* src) {
    asm volatile("cp.async.cg.shared.global [%0], [%1], 16;" :: "r"(dst), "l"(src));
}
__device__ __forceinline__ void ldsm4(uint32_t (&r)[4], uint32_t addr) {
    asm volatile("ldmatrix.sync.aligned.m8n8.x4.shared.b16 {%0,%1,%2,%3}, [%4];"
        : "=r"(r[0]), "=r"(r[1]), "=r"(r[2]), "=r"(r[3]) : "r"(addr));
}
__device__ __forceinline__ void ldsm4t(uint32_t (&r)[4], uint32_t addr) {
    asm volatile("ldmatrix.sync.aligned.m8n8.x4.trans.shared.b16 {%0,%1,%2,%3}, [%4];"
        : "=r"(r[0]), "=r"(r[1]), "=r"(r[2]), "=r"(r[3]) : "r"(addr));
}
// fp16 inputs, fp32 accum
__device__ __forceinline__ void mma16816(float (&c)[4], const uint32_t (&a)[4],
                                         uint32_t b0, uint32_t b1) {
    asm volatile("mma.sync.aligned.m16n8k16.row.col.f32.f16.f16.f32 "
        "{%0,%1,%2,%3}, {%4,%5,%6,%7}, {%8,%9}, {%0,%1,%2,%3};"
        : "+f"(c[0]), "+f"(c[1]), "+f"(c[2]), "+f"(c[3])
        : "r"(a[0]), "r"(a[1]), "r"(a[2]), "r"(a[3]), "r"(b0), "r"(b1));
}
__device__ __forceinline__ uint32_t h2u(__half2 v) {
    return *reinterpret_cast<uint32_t*>(&v);
}
// split two floats into packed fp16x2 hi + lo-residual
__device__ __forceinline__ void split_pack2(float a, float b, uint32_t& h, uint32_t& l) {
    __half2 hh = __floats2half2_rn(a, b);
    h = h2u(hh);
    float ra = a - __half2float(__low2half(hh));
    float rb = b - __half2float(__high2half(hh));
    __half2 ll = __floats2half2_rn(ra, rb);
    l = h2u(ll);
}
__device__ __forceinline__ uint32_t swz128(uint32_t off) { return off ^ ((off >> 3) & 0x70); }

// =====================================================================
// mma_gemm: C = (Ah+Al)[M,K] @ B[N,K]^T + bias   (A split fp16, B single fp16)
// epi: 0=none, 1=GELU(exact), 2=+res. fused!=0: N=3072 QKV routing.
// 128x128 CTA tile, BK=64, 3-stage cp.async, 8 warps, 2 MMA passes.
// =====================================================================
#define GTILEB 16384                  // 128 rows x 128 B
#define GSTAGEB (3 * GTILEB)          // Ah, Al, B = 48 KB
#define SMEM_MMA (3 * GSTAGEB + 1024)

__global__ __launch_bounds__(256, 1)
void mma_gemm(const __half* __restrict__ Ah, const __half* __restrict__ Al,
              const __half* __restrict__ B,
              const float* __restrict__ bias, const float* __restrict__ res,
              float* __restrict__ Cf,
              __half* __restrict__ Ch0, __half* __restrict__ Cl0,
              __half* __restrict__ Ch1, __half* __restrict__ Cl1,
              __half* __restrict__ Ch2, __half* __restrict__ Cl2,
              int M, int N, int K, int outN, int epi, int fused)
{
    extern __shared__ char smem[];
    const uint32_t s0 = (smem_u32(smem) + 1023) & ~1023u;

    const int tid = threadIdx.x;
    const int wid = tid >> 5, lid = tid & 31;
    const int brow = blockIdx.y << 7, bcol = blockIdx.x << 7;
    const int mw = (wid & 3) << 5;
    const int nw = (wid >> 2) << 6;

    const int lrow  = tid >> 1;
    const int lhalf = tid & 1;
    uint32_t sw[4];
#pragma unroll
    for (int i = 0; i < 4; i++)
        sw[i] = swz128(lrow * 128 + lhalf * 64 + i * 16);
    const size_t ga = (size_t)(brow + lrow) * K + lhalf * 32;
    const size_t gb = (size_t)(bcol + lrow) * K + lhalf * 32;

    const int nchunk = K >> 6;

    auto issue = [&](int c) {
        const uint32_t st = s0 + (uint32_t)(c % 3) * GSTAGEB;
        const size_t k0 = (size_t)c << 6;
#pragma unroll
        for (int i = 0; i < 4; i++) {
            cpasync16(st + 0 * GTILEB + sw[i], Ah + ga + k0 + i * 8);
            cpasync16(st + 1 * GTILEB + sw[i], Al + ga + k0 + i * 8);
            cpasync16(st + 2 * GTILEB + sw[i], B  + gb + k0 + i * 8);
        }
    };

    issue(0);
    asm volatile("cp.async.commit_group;");
    issue(1);
    asm volatile("cp.async.commit_group;");

    float acc[2][8][4];
#pragma unroll
    for (int i = 0; i < 2; i++)
#pragma unroll
        for (int j = 0; j < 8; j++)
#pragma unroll
            for (int t = 0; t < 4; t++) acc[i][j][t] = 0.f;

    const int a_row = lid & 15;
    const int a_h   = (lid >> 4) * 16;
    const int b_row = (lid & 7) + ((lid >> 4) << 3);
    const int b_h   = ((lid >> 3) & 1) * 16;

    for (int c = 0; c < nchunk; c++) {
        asm volatile("cp.async.wait_group 1;");
        __syncthreads();
        if (c + 2 < nchunk) issue(c + 2);
        asm volatile("cp.async.commit_group;");

        const uint32_t st  = s0 + (uint32_t)(c % 3) * GSTAGEB;
        const uint32_t sAh = st, sAl = st + GTILEB;
        const uint32_t sB  = st + 2 * GTILEB;

#pragma unroll
        for (int ks = 0; ks < 4; ks++) {
            uint32_t ah[2][4], al[2][4];
#pragma unroll
            for (int i = 0; i < 2; i++) {
                uint32_t off = swz128((mw + i * 16 + a_row) * 128 + ks * 32 + a_h);
                ldsm4(ah[i], sAh + off);
                ldsm4(al[i], sAl + off);
            }
            uint32_t bf[8][2];
#pragma unroll
            for (int jj = 0; jj < 4; jj++) {
                uint32_t off = swz128((nw + jj * 16 + b_row) * 128 + ks * 32 + b_h);
                uint32_t t0[4];
                ldsm4(t0, sB + off);
                bf[2*jj][0] = t0[0]; bf[2*jj][1] = t0[1];
                bf[2*jj+1][0] = t0[2]; bf[2*jj+1][1] = t0[3];
            }
#pragma unroll
            for (int i = 0; i < 2; i++)
#pragma unroll
                for (int j = 0; j < 8; j++) {
                    mma16816(acc[i][j], ah[i], bf[j][0], bf[j][1]);
                    mma16816(acc[i][j], al[i], bf[j][0], bf[j][1]);
                }
        }
    }

    // ---- epilogue ----
    int sel = fused ? (bcol >> 10) : 0;
    const int nbase = fused ? (bcol & 1023) : bcol;
    __half* Ch = (sel == 0) ? Ch0 : (sel == 1) ? Ch1 : Ch2;
    __half* Cl = (sel == 0) ? Cl0 : (sel == 1) ? Cl1 : Cl2;

    const int erow = lid >> 2;
    const int ecol = (lid & 3) << 1;
#pragma unroll
    for (int i = 0; i < 2; i++)
#pragma unroll
        for (int j = 0; j < 8; j++)
#pragma unroll
            for (int h = 0; h < 2; h++) {
                const int m = brow + mw + i * 16 + erow + h * 8;
                const int ng = bcol + nw + j * 8 + ecol;
                const int nl = nbase + nw + j * 8 + ecol;
                float v0 = acc[i][j][h * 2 + 0] + bias[ng];
                float v1 = acc[i][j][h * 2 + 1] + bias[ng + 1];
                const size_t off = (size_t)m * outN + nl;
                if (epi == 1) {
                    v0 = 0.5f * v0 * (1.0f + erff(v0 * 0.70710678118654752f));
                    v1 = 0.5f * v1 * (1.0f + erff(v1 * 0.70710678118654752f));
                } else if (epi == 2) {
                    float2 rr = *(const float2*)&res[off];
                    v0 += rr.x; v1 += rr.y;
                }
                if (Cf) *(float2*)&Cf[off] = make_float2(v0, v1);
                if (Ch) {
                    uint32_t hh, ll;
                    split_pack2(v0, v1, hh, ll);
                    *(uint32_t*)&Ch[off] = hh;
                    *(uint32_t*)&Cl[off] = ll;
                }
            }
}

// =====================================================================
// Causal flash attention via HMMA fp16 hi/lo split (3-pass). fp32 softmax.
// =====================================================================
#define ATT_STAGEB 32768
#define SMEM_ATT (1024 + 32768 + 3 * ATT_STAGEB)

__global__ __launch_bounds__(256, 1)
void attn_mma(const __half* __restrict__ Qh, const __half* __restrict__ Ql,
              const __half* __restrict__ Kh, const __half* __restrict__ Kl,
              const __half* __restrict__ Vh, const __half* __restrict__ Vl,
              __half* __restrict__ Oh, __half* __restrict__ Ol)
{
    extern __shared__ char sm[];
    const uint32_t sQh = (smem_u32(sm) + 1023) & ~1023u;
    const uint32_t sQl = sQh + 16384;
    const uint32_t sKV = sQh + 32768;

    const int tid = threadIdx.x, wid = tid >> 5, lid = tid & 31;
    const int qt = (int)gridDim.x - 1 - (int)blockIdx.x;
    const int bh = blockIdx.y;
    const int b = bh >> 4, h = bh & 15;
    const int qbase = qt * 128;
    const size_t tok0 = (size_t)b * SEQ;
    const size_t hoff = (size_t)h * 64;
    const int mw = wid * 16;

    {
        const int r = tid >> 1;
        const int half = tid & 1;
        const size_t g = (tok0 + qbase + r) * DM + hoff + half * 32;
#pragma unroll
        for (int i = 0; i < 4; i++) {
            uint32_t so = swz128(r * 128 + half * 64 + i * 16);
            cpasync16(sQh + so, Qh + g + i * 8);
            cpasync16(sQl + so, Ql + g + i * 8);
        }
    }

    const int njt = 2 * qt + 2;
    const int kr = tid >> 2;
    const int kq = tid & 3;
    const uint32_t kso0 = swz128(kr * 128 + kq * 32);
    const uint32_t kso1 = swz128(kr * 128 + kq * 32 + 16);

    auto issue_kv = [&](int jt) {
        const uint32_t st = sKV + (uint32_t)(jt % 3) * ATT_STAGEB;
        const size_t g = (tok0 + jt * 64 + kr) * DM + hoff + kq * 16;
        cpasync16(st +         kso0, Kh + g);
        cpasync16(st +         kso1, Kh + g + 8);
        cpasync16(st +  8192 + kso0, Kl + g);
        cpasync16(st +  8192 + kso1, Kl + g + 8);
        cpasync16(st + 16384 + kso0, Vh + g);
        cpasync16(st + 16384 + kso1, Vh + g + 8);
        cpasync16(st + 24576 + kso0, Vl + g);
        cpasync16(st + 24576 + kso1, Vl + g + 8);
    };

    issue_kv(0);
    asm volatile("cp.async.commit_group;");
    issue_kv(1);
    asm volatile("cp.async.commit_group;");

    float O[8][4];
#pragma unroll
    for (int j = 0; j < 8; j++)
#pragma unroll
        for (int e = 0; e < 4; e++) O[j][e] = 0.f;
    float m0 = -1e30f, m1 = -1e30f, l0 = 0.f, l1 = 0.f;

    const int rql = lid >> 2;
    const int cql = (lid & 3) * 2;
    const int row0g = qbase + mw + rql;
    const int row1g = row0g + 8;

    for (int jt = 0; jt < njt; jt++) {
        asm volatile("cp.async.wait_group 1;");
        __syncthreads();
        if (jt + 2 < njt) issue_kv(jt + 2);
        asm volatile("cp.async.commit_group;");

        const bool active = !(mw < 64 && jt == njt - 1);
        if (active) {
            const uint32_t stKh = sKV + (uint32_t)(jt % 3) * ATT_STAGEB;
            const uint32_t stKl = stKh + 8192;
            const uint32_t stVh = stKh + 16384, stVl = stKh + 24576;

            float S[8][4];
#pragma unroll
            for (int j = 0; j < 8; j++)
#pragma unroll
                for (int e = 0; e < 4; e++) S[j][e] = 0.f;

#pragma unroll
            for (int ks = 0; ks < 4; ks++) {
                uint32_t qh4[4], ql4[4];
                uint32_t qoff = swz128((mw + (lid & 15)) * 128 + ks * 32 + (lid >> 4) * 16);
                ldsm4(qh4, sQh + qoff);
                ldsm4(ql4, sQl + qoff);
                uint32_t kfh[8][2], kfl[8][2];
#pragma unroll
                for (int jj = 0; jj < 4; jj++) {
                    uint32_t koff = swz128((jj * 16 + (lid & 7) + ((lid >> 4) << 3)) * 128
                                           + ks * 32 + ((lid >> 3) & 1) * 16);
                    uint32_t t0[4], t1[4];
                    ldsm4(t0, stKh + koff);
                    ldsm4(t1, stKl + koff);
                    kfh[2*jj][0]=t0[0]; kfh[2*jj][1]=t0[1]; kfh[2*jj+1][0]=t0[2]; kfh[2*jj+1][1]=t0[3];
                    kfl[2*jj][0]=t1[0]; kfl[2*jj][1]=t1[1]; kfl[2*jj+1][0]=t1[2]; kfl[2*jj+1][1]=t1[3];
                }
#pragma unroll
                for (int j = 0; j < 8; j++) mma16816(S[j], qh4, kfh[j][0], kfh[j][1]);
#pragma unroll
                for (int j = 0; j < 8; j++) mma16816(S[j], qh4, kfl[j][0], kfl[j][1]);
#pragma unroll
                for (int j = 0; j < 8; j++) mma16816(S[j], ql4, kfh[j][0], kfh[j][1]);
            }

            const int colb = jt * 64;
            const bool diag = (jt >= 2 * qt);
#pragma unroll
            for (int j = 0; j < 8; j++)
#pragma unroll
                for (int e = 0; e < 4; e++) {
                    float v = S[j][e] * 0.125f;
                    if (diag) {
                        int col = colb + 8 * j + cql + (e & 1);
                        int row = (e < 2) ? row0g : row1g;
                        if (col > row) v = -1e30f;
                    }
                    S[j][e] = v;
                }

            float rm0 = -1e30f, rm1 = -1e30f;
#pragma unroll
            for (int j = 0; j < 8; j++) {
                rm0 = fmaxf(rm0, fmaxf(S[j][0], S[j][1]));
                rm1 = fmaxf(rm1, fmaxf(S[j][2], S[j][3]));
            }
            rm0 = fmaxf(rm0, __shfl_xor_sync(0xffffffffu, rm0, 1));
            rm0 = fmaxf(rm0, __shfl_xor_sync(0xffffffffu, rm0, 2));
            rm1 = fmaxf(rm1, __shfl_xor_sync(0xffffffffu, rm1, 1));
            rm1 = fmaxf(rm1, __shfl_xor_sync(0xffffffffu, rm1, 2));
            float mn0 = fmaxf(m0, rm0), mn1 = fmaxf(m1, rm1);
            float a0 = __expf(m0 - mn0), a1 = __expf(m1 - mn1);
            m0 = mn0; m1 = mn1;
            float rs0 = 0.f, rs1 = 0.f;
#pragma unroll
            for (int j = 0; j < 8; j++) {
                S[j][0] = __expf(S[j][0] - mn0);
                S[j][1] = __expf(S[j][1] - mn0);
                S[j][2] = __expf(S[j][2] - mn1);
                S[j][3] = __expf(S[j][3] - mn1);
                rs0 += S[j][0] + S[j][1];
                rs1 += S[j][2] + S[j][3];
            }
            rs0 += __shfl_xor_sync(0xffffffffu, rs0, 1);
            rs0 += __shfl_xor_sync(0xffffffffu, rs0, 2);
            rs1 += __shfl_xor_sync(0xffffffffu, rs1, 1);
            rs1 += __shfl_xor_sync(0xffffffffu, rs1, 2);
            l0 = l0 * a0 + rs0;
            l1 = l1 * a1 + rs1;
#pragma unroll
            for (int j = 0; j < 8; j++) {
                O[j][0] *= a0; O[j][1] *= a0; O[j][2] *= a1; O[j][3] *= a1;
            }

            uint32_t pah[4][4], pal[4][4];
#pragma unroll
            for (int ks = 0; ks < 4; ks++) {
                split_pack2(S[2*ks][0],   S[2*ks][1],   pah[ks][0], pal[ks][0]);
                split_pack2(S[2*ks][2],   S[2*ks][3],   pah[ks][1], pal[ks][1]);
                split_pack2(S[2*ks+1][0], S[2*ks+1][1], pah[ks][2], pal[ks][2]);
                split_pack2(S[2*ks+1][2], S[2*ks+1][3], pah[ks][3], pal[ks][3]);
            }

#pragma unroll
            for (int ks = 0; ks < 4; ks++) {
                uint32_t vfh[8][2], vfl[8][2];
                const int rowv = ks * 16 + ((lid >> 3) & 1) * 8 + (lid & 7);
                const int colv = (lid >> 4) * 16;
#pragma unroll
                for (int nb = 0; nb < 4; nb++) {
                    uint32_t voff = swz128(rowv * 128 + nb * 32 + colv);
                    uint32_t t0[4], t1[4];
                    ldsm4t(t0, stVh + voff);
                    ldsm4t(t1, stVl + voff);
                    vfh[2*nb][0]=t0[0]; vfh[2*nb][1]=t0[1]; vfh[2*nb+1][0]=t0[2]; vfh[2*nb+1][1]=t0[3];
                    vfl[2*nb][0]=t1[0]; vfl[2*nb][1]=t1[1]; vfl[2*nb+1][0]=t1[2]; vfl[2*nb+1][1]=t1[3];
                }
#pragma unroll
                for (int j = 0; j < 8; j++) mma16816(O[j], pah[ks], vfh[j][0], vfh[j][1]);
#pragma unroll
                for (int j = 0; j < 8; j++) mma16816(O[j], pah[ks], vfl[j][0], vfl[j][1]);
#pragma unroll
                for (int j = 0; j < 8; j++) mma16816(O[j], pal[ks], vfh[j][0], vfh[j][1]);
            }
        }
    }

    const float inv0 = 1.0f / l0, inv1 = 1.0f / l1;
    const size_t tq0 = (tok0 + row0g) * DM + hoff;
    const size_t tq1 = (tok0 + row1g) * DM + hoff;
#pragma unroll
    for (int j = 0; j < 8; j++) {
        const int c = 8 * j + cql;
        uint32_t hh, ll;
        split_pack2(O[j][0] * inv0, O[j][1] * inv0, hh, ll);
        *(uint32_t*)&Oh[tq0 + c] = hh;
        *(uint32_t*)&Ol[tq0 + c] = ll;
        split_pack2(O[j][2] * inv1, O[j][3] * inv1, hh, ll);
        *(uint32_t*)&Oh[tq1 + c] = hh;
        *(uint32_t*)&Ol[tq1 + c] = ll;
    }
}

// =====================================================================
// conversions
// =====================================================================
__global__ __launch_bounds__(256)
void conv_act(const float* __restrict__ in, __half* __restrict__ hi,
              __half* __restrict__ lo)
{
    const size_t i = ((size_t)blockIdx.x * 256 + threadIdx.x) * 4;
    float4 v = *(const float4*)(in + i);
    uint32_t h0, l0, h1, l1;
    split_pack2(v.x, v.y, h0, l0);
    split_pack2(v.z, v.w, h1, l1);
    *(uint32_t*)&hi[i]     = h0;
    *(uint32_t*)&hi[i + 2] = h1;
    *(uint32_t*)&lo[i]     = l0;
    *(uint32_t*)&lo[i + 2] = l1;
}

// transpose W[K,N] -> fp16 [N,K]
__global__ __launch_bounds__(256)
void conv_wT(const float* __restrict__ W, __half* __restrict__ hi, int K, int N)
{
    __shared__ float t[32][33];
    const int n0 = blockIdx.x * 32, k0 = blockIdx.y * 32;
    const int tx = threadIdx.x & 31, ty = threadIdx.x >> 5;
#pragma unroll
    for (int j = 0; j < 4; j++)
        t[ty + 8 * j][tx] = W[(size_t)(k0 + ty + 8 * j) * N + n0 + tx];
    __syncthreads();
#pragma unroll
    for (int j = 0; j < 4; j++) {
        size_t o = (size_t)(n0 + ty + 8 * j) * K + k0 + tx;
        hi[o] = __float2half_rn(t[tx][ty + 8 * j]);
    }
}

// fused QKV weight transpose: Wq/Wk/Wv [1024,1024] -> wqkv [3072,1024] fp16
__global__ __launch_bounds__(256)
void conv_wT3(const float* __restrict__ W0, const float* __restrict__ W1,
              const float* __restrict__ W2, __half* __restrict__ hi)
{
    __shared__ float t[32][33];
    const int n0 = blockIdx.x * 32, k0 = blockIdx.y * 32;
    const int sel = n0 >> 10;
    const int nl = n0 & 1023;
    const float* W = (sel == 0) ? W0 : (sel == 1) ? W1 : W2;
    const int tx = threadIdx.x & 31, ty = threadIdx.x >> 5;
#pragma unroll
    for (int j = 0; j < 4; j++)
        t[ty + 8 * j][tx] = W[(size_t)(k0 + ty + 8 * j) * 1024 + nl + tx];
    __syncthreads();
#pragma unroll
    for (int j = 0; j < 4; j++) {
        size_t o = (size_t)(n0 + ty + 8 * j) * 1024 + k0 + tx;
        hi[o] = __float2half_rn(t[tx][ty + 8 * j]);
    }
}

__global__ void bias_cat(const float* __restrict__ b0, const float* __restrict__ b1,
                         const float* __restrict__ b2, float* __restrict__ out)
{
    int i = blockIdx.x * 256 + threadIdx.x;
    out[i] = (i < 1024) ? b0[i] : (i < 2048) ? b1[i - 1024] : b2[i - 2048];
}

// =====================================================================
// LayerNorm (+ optional fp16 hi/lo split out)
// =====================================================================
__global__ __launch_bounds__(256)
void ln_kernel(const float* __restrict__ in, const float* __restrict__ gamma,
               const float* __restrict__ beta, float* __restrict__ out,
               __half* __restrict__ oh, __half* __restrict__ ol)
{
    __shared__ float rs[8], rs2[8];
    const int row = blockIdx.x;
    const int t = threadIdx.x;
    float4 v = ((const float4*)(in + (size_t)row * DM))[t];
    float s  = v.x + v.y + v.z + v.w;
    float s2 = v.x * v.x + v.y * v.y + v.z * v.z + v.w * v.w;
#pragma unroll
    for (int off = 16; off; off >>= 1) {
        s  += __shfl_xor_sync(0xffffffffu, s, off);
        s2 += __shfl_xor_sync(0xffffffffu, s2, off);
    }
    if ((t & 31) == 0) { rs[t >> 5] = s; rs2[t >> 5] = s2; }
    __syncthreads();
    float ts = 0.f, ts2 = 0.f;
#pragma unroll
    for (int w = 0; w < 8; w++) { ts += rs[w]; ts2 += rs2[w]; }
    float mu   = ts * (1.0f / DM);
    float var  = ts2 * (1.0f / DM) - mu * mu;
    float rstd = rsqrtf(var + 1e-5f);
    float4 g4 = ((const float4*)gamma)[t];
    float4 b4 = ((const float4*)beta)[t];
    float4 o4;
    o4.x = (v.x - mu) * rstd * g4.x + b4.x;
    o4.y = (v.y - mu) * rstd * g4.y + b4.y;
    o4.z = (v.z - mu) * rstd * g4.z + b4.z;
    o4.w = (v.w - mu) * rstd * g4.w + b4.w;
    ((float4*)(out + (size_t)row * DM))[t] = o4;
    if (oh) {
        const size_t i = (size_t)row * DM + t * 4;
        uint32_t h0, l0, h1, l1;
        split_pack2(o4.x, o4.y, h0, l0);
        split_pack2(o4.z, o4.w, h1, l1);
        *(uint32_t*)&oh[i]     = h0;
        *(uint32_t*)&oh[i + 2] = h1;
        *(uint32_t*)&ol[i]     = l0;
        *(uint32_t*)&ol[i + 2] = l1;
    }
}

// =====================================================================
extern "C" void kernel_launch(void* const* d_in, const int* in_sizes, int n_in,
                              void* d_out, int out_size)
{
    (void)in_sizes; (void)n_in; (void)out_size;
    const float* x   = (const float*)d_in[0];
    const float* Wq  = (const float*)d_in[1];
    const float* bq  = (const float*)d_in[2];
    const float* Wk  = (const float*)d_in[3];
    const float* bk  = (const float*)d_in[4];
    const float* Wv  = (const float*)d_in[5];
    const float* bv  = (const float*)d_in[6];
    const float* Wo  = (const float*)d_in[7];
    const float* bo  = (const float*)d_in[8];
    const float* W1  = (const float*)d_in[9];
    const float* b1  = (const float*)d_in[10];
    const float* W2  = (const float*)d_in[11];
    const float* b2  = (const float*)d_in[12];
    const float* g1  = (const float*)d_in[13];
    const float* be1 = (const float*)d_in[14];
    const float* g2  = (const float*)d_in[15];
    const float* be2 = (const float*)d_in[16];
    float* out = (float*)d_out;

    float *gt0, *gx1, *gbqkv;
    cudaGetSymbolAddress((void**)&gt0, g_t0);
    cudaGetSymbolAddress((void**)&gx1, g_x1);
    cudaGetSymbolAddress((void**)&gbqkv, g_bqkv);

    __half *xh, *xl, *qh, *ql, *kh, *kl, *vh, *vl, *ctxh, *ctxl, *x1h, *x1l, *ffh, *ffl;
    __half *wqkvh, *woh, *w1h, *w2h;
    cudaGetSymbolAddress((void**)&xh,    g_xh);    cudaGetSymbolAddress((void**)&xl,    g_xl);
    cudaGetSymbolAddress((void**)&qh,    g_qh);    cudaGetSymbolAddress((void**)&ql,    g_ql);
    cudaGetSymbolAddress((void**)&kh,    g_kh);    cudaGetSymbolAddress((void**)&kl,    g_kl);
    cudaGetSymbolAddress((void**)&vh,    g_vh);    cudaGetSymbolAddress((void**)&vl,    g_vl);
    cudaGetSymbolAddress((void**)&ctxh,  g_ctxh);  cudaGetSymbolAddress((void**)&ctxl,  g_ctxl);
    cudaGetSymbolAddress((void**)&x1h,   g_x1h);   cudaGetSymbolAddress((void**)&x1l,   g_x1l);
    cudaGetSymbolAddress((void**)&ffh,   g_ffh);   cudaGetSymbolAddress((void**)&ffl,   g_ffl);
    cudaGetSymbolAddress((void**)&wqkvh, g_wqkvh);
    cudaGetSymbolAddress((void**)&woh,   g_woh);
    cudaGetSymbolAddress((void**)&w1h,   g_w1h);
    cudaGetSymbolAddress((void**)&w2h,   g_w2h);

    cudaFuncSetAttribute(mma_gemm, cudaFuncAttributeMaxDynamicSharedMemorySize, SMEM_MMA);
    cudaFuncSetAttribute(attn_mma, cudaFuncAttributeMaxDynamicSharedMemorySize, SMEM_ATT);

    // ---- weight prep (fp16 single) ----
    conv_wT3<<<dim3(3 * DM / 32, DM / 32), 256>>>(Wq, Wk, Wv, wqkvh);
    conv_wT<<<dim3(DM / 32,  DM / 32),  256>>>(Wo, woh, DM, DM);
    conv_wT<<<dim3(DFF / 32, DM / 32),  256>>>(W1, w1h, DM, DFF);
    conv_wT<<<dim3(DM / 32,  DFF / 32), 256>>>(W2, w2h, DFF, DM);
    bias_cat<<<12, 256>>>(bq, bk, bv, gbqkv);

    // ---- x split ----
    conv_act<<<(NTOK * DM) / 1024, 256>>>(x, xh, xl);

    // ---- fused QKV GEMM (N=3072) ----
    mma_gemm<<<dim3(3 * DM / 128, NTOK / 128), 256, SMEM_MMA>>>(
        xh, xl, wqkvh, gbqkv, nullptr, nullptr,
        qh, ql, kh, kl, vh, vl, NTOK, 3 * DM, DM, DM, 0, 1);

    // ---- attention ----
    attn_mma<<<dim3(SEQ / 128, 32), 256, SMEM_ATT>>>(qh, ql, kh, kl, vh, vl, ctxh, ctxl);

    // ---- Wo + residual, LN1 (+split) ----
    mma_gemm<<<dim3(DM / 128, NTOK / 128), 256, SMEM_MMA>>>(
        ctxh, ctxl, woh, bo, x, gt0,
        nullptr, nullptr, nullptr, nullptr, nullptr, nullptr, NTOK, DM, DM, DM, 2, 0);
    ln_kernel<<<NTOK, 256>>>(gt0, g1, be1, gx1, x1h, x1l);

    // ---- FFN ----
    mma_gemm<<<dim3(DFF / 128, NTOK / 128), 256, SMEM_MMA>>>(
        x1h, x1l, w1h, b1, nullptr, nullptr,
        ffh, ffl, nullptr, nullptr, nullptr, nullptr, NTOK, DFF, DM, DFF, 1, 0);
    mma_gemm<<<dim3(DM / 128, NTOK / 128), 256, SMEM_MMA>>>(
        ffh, ffl, w2h, b2, gx1, gt0,
        nullptr, nullptr, nullptr, nullptr, nullptr, nullptr, NTOK, DM, DFF, DM, 2, 0);
    ln_kernel<<<NTOK, 256>>>(gt0, g2, be2, out, nullptr, nullptr);
}

// round 13
// speedup vs baseline: 2.1836x; 1.6418x over previous
#include <cuda_runtime.h>
#include <cuda_fp16.h>
#include <cstdint>

#define NTOK 4096   // B*L
#define DM   1024
#define DFF  4096
#define SEQ  2048

// ---------------- scratch (device globals: allocation-free) ----------------
__device__ float g_t0[NTOK * DM];
__device__ float g_x1[NTOK * DM];

__device__ __half g_xh[NTOK * DM];
__device__ __half g_qh[NTOK * DM];
__device__ __half g_kh[NTOK * DM];
__device__ __half g_vh[NTOK * DM];
__device__ __half g_ctxh[NTOK * DM];
__device__ __half g_x1h[NTOK * DM];
__device__ __half g_ffh[(size_t)NTOK * DFF];
__device__ __half g_wqkvh[3 * DM * DM];
__device__ float g_bqkv[3 * DM];
__device__ __half g_woh[DM * DM];
__device__ __half g_w1h[(size_t)DFF * DM];
__device__ __half g_w2h[(size_t)DM * DFF];

// ---------------- PTX helpers (family-portable; NO tcgen05) ----------------
__device__ __forceinline__ uint32_t smem_u32(const void* p) {
    uint32_t a;
    asm("{ .reg .u64 t; cvta.to.shared.u64 t, %1; cvt.u32.u64 %0, t; }" : "=r"(a) : "l"(p));
    return a;
}
__device__ __forceinline__ void cpasync16(uint32_t dst, const void* src) {
    asm volatile("cp.async.cg.shared.global [%0], [%1], 16;" :: "r"(dst), "l"(src));
}
__device__ __forceinline__ void ldsm4(uint32_t (&r)[4], uint32_t addr) {
    asm volatile("ldmatrix.sync.aligned.m8n8.x4.shared.b16 {%0,%1,%2,%3}, [%4];"
        : "=r"(r[0]), "=r"(r[1]), "=r"(r[2]), "=r"(r[3]) : "r"(addr));
}
__device__ __forceinline__ void ldsm4t(uint32_t (&r)[4], uint32_t addr) {
    asm volatile("ldmatrix.sync.aligned.m8n8.x4.trans.shared.b16 {%0,%1,%2,%3}, [%4];"
        : "=r"(r[0]), "=r"(r[1]), "=r"(r[2]), "=r"(r[3]) : "r"(addr));
}
__device__ __forceinline__ void mma16816(float (&c)[4], const uint32_t (&a)[4],
                                         uint32_t b0, uint32_t b1) {
    asm volatile("mma.sync.aligned.m16n8k16.row.col.f32.f16.f16.f32 "
        "{%0,%1,%2,%3}, {%4,%5,%6,%7}, {%8,%9}, {%0,%1,%2,%3};"
        : "+f"(c[0]), "+f"(c[1]), "+f"(c[2]), "+f"(c[3])
        : "r"(a[0]), "r"(a[1]), "r"(a[2]), "r"(a[3]), "r"(b0), "r"(b1));
}
__device__ __forceinline__ uint32_t h2u(__half2 v) {
    return *reinterpret_cast<uint32_t*>(&v);
}
__device__ __forceinline__ uint32_t pack2(float a, float b) {
    __half2 h = __floats2half2_rn(a, b);
    return h2u(h);
}
__device__ __forceinline__ uint32_t swz128(uint32_t off) { return off ^ ((off >> 3) & 0x70); }

// =====================================================================
// mma_gemm: C = A[M,K] @ B[N,K]^T + bias   (A,B single fp16, fp32 accum)
// epi: 0=none, 1=GELU(exact), 2=+res. fused!=0: N=3072 QKV routing.
// 128x128 CTA tile, BK=64, 3-stage cp.async, 8 warps, 1 MMA pass.
// =====================================================================
#define GTILEB 16384                  // 128 rows x 128 B
#define GSTAGEB (2 * GTILEB)          // A, B = 32 KB
#define SMEM_MMA (3 * GSTAGEB + 1024)

__global__ __launch_bounds__(256, 1)
void mma_gemm(const __half* __restrict__ A, const __half* __restrict__ B,
              const float* __restrict__ bias, const float* __restrict__ res,
              float* __restrict__ Cf,
              __half* __restrict__ Ch0, __half* __restrict__ Ch1,
              __half* __restrict__ Ch2,
              int M, int N, int K, int outN, int epi, int fused)
{
    extern __shared__ char smem[];
    const uint32_t s0 = (smem_u32(smem) + 1023) & ~1023u;

    const int tid = threadIdx.x;
    const int wid = tid >> 5, lid = tid & 31;
    const int brow = blockIdx.y << 7, bcol = blockIdx.x << 7;
    const int mw = (wid & 3) << 5;
    const int nw = (wid >> 2) << 6;

    const int lrow  = tid >> 1;
    const int lhalf = tid & 1;
    uint32_t sw[4];
#pragma unroll
    for (int i = 0; i < 4; i++)
        sw[i] = swz128(lrow * 128 + lhalf * 64 + i * 16);
    const size_t ga = (size_t)(brow + lrow) * K + lhalf * 32;
    const size_t gb = (size_t)(bcol + lrow) * K + lhalf * 32;

    const int nchunk = K >> 6;

    auto issue = [&](int c) {
        const uint32_t st = s0 + (uint32_t)(c % 3) * GSTAGEB;
        const size_t k0 = (size_t)c << 6;
#pragma unroll
        for (int i = 0; i < 4; i++) {
            cpasync16(st +          sw[i], A + ga + k0 + i * 8);
            cpasync16(st + GTILEB + sw[i], B + gb + k0 + i * 8);
        }
    };

    issue(0);
    asm volatile("cp.async.commit_group;");
    issue(1);
    asm volatile("cp.async.commit_group;");

    float acc[2][8][4];
#pragma unroll
    for (int i = 0; i < 2; i++)
#pragma unroll
        for (int j = 0; j < 8; j++)
#pragma unroll
            for (int t = 0; t < 4; t++) acc[i][j][t] = 0.f;

    const int a_row = lid & 15;
    const int a_h   = (lid >> 4) * 16;
    const int b_row = (lid & 7) + ((lid >> 4) << 3);
    const int b_h   = ((lid >> 3) & 1) * 16;

    for (int c = 0; c < nchunk; c++) {
        asm volatile("cp.async.wait_group 1;");
        __syncthreads();
        if (c + 2 < nchunk) issue(c + 2);
        asm volatile("cp.async.commit_group;");

        const uint32_t st = s0 + (uint32_t)(c % 3) * GSTAGEB;
        const uint32_t sA = st, sB = st + GTILEB;

#pragma unroll
        for (int ks = 0; ks < 4; ks++) {
            uint32_t af[2][4];
#pragma unroll
            for (int i = 0; i < 2; i++) {
                uint32_t off = swz128((mw + i * 16 + a_row) * 128 + ks * 32 + a_h);
                ldsm4(af[i], sA + off);
            }
            uint32_t bf[8][2];
#pragma unroll
            for (int jj = 0; jj < 4; jj++) {
                uint32_t off = swz128((nw + jj * 16 + b_row) * 128 + ks * 32 + b_h);
                uint32_t t0[4];
                ldsm4(t0, sB + off);
                bf[2*jj][0] = t0[0]; bf[2*jj][1] = t0[1];
                bf[2*jj+1][0] = t0[2]; bf[2*jj+1][1] = t0[3];
            }
#pragma unroll
            for (int i = 0; i < 2; i++)
#pragma unroll
                for (int j = 0; j < 8; j++)
                    mma16816(acc[i][j], af[i], bf[j][0], bf[j][1]);
        }
    }

    // ---- epilogue ----
    int sel = fused ? (bcol >> 10) : 0;
    const int nbase = fused ? (bcol & 1023) : bcol;
    __half* Ch = (sel == 0) ? Ch0 : (sel == 1) ? Ch1 : Ch2;

    const int erow = lid >> 2;
    const int ecol = (lid & 3) << 1;
#pragma unroll
    for (int i = 0; i < 2; i++)
#pragma unroll
        for (int j = 0; j < 8; j++)
#pragma unroll
            for (int h = 0; h < 2; h++) {
                const int m = brow + mw + i * 16 + erow + h * 8;
                const int ng = bcol + nw + j * 8 + ecol;
                const int nl = nbase + nw + j * 8 + ecol;
                float v0 = acc[i][j][h * 2 + 0] + bias[ng];
                float v1 = acc[i][j][h * 2 + 1] + bias[ng + 1];
                const size_t off = (size_t)m * outN + nl;
                if (epi == 1) {
                    v0 = 0.5f * v0 * (1.0f + erff(v0 * 0.70710678118654752f));
                    v1 = 0.5f * v1 * (1.0f + erff(v1 * 0.70710678118654752f));
                } else if (epi == 2) {
                    float2 rr = *(const float2*)&res[off];
                    v0 += rr.x; v1 += rr.y;
                }
                if (Cf) *(float2*)&Cf[off] = make_float2(v0, v1);
                if (Ch) *(uint32_t*)&Ch[off] = pack2(v0, v1);
            }
}

// =====================================================================
// Causal flash attention, pure fp16 HMMA (single precision per operand),
// fp32 softmax/accumulators.
// =====================================================================
#define ATT_STAGEB 16384              // K 8K + V 8K per stage
#define SMEM_ATT (1024 + 16384 + 3 * ATT_STAGEB)

__global__ __launch_bounds__(256, 2)
void attn_mma(const __half* __restrict__ Q, const __half* __restrict__ K,
              const __half* __restrict__ V, __half* __restrict__ O_)
{
    extern __shared__ char sm[];
    const uint32_t sQ  = (smem_u32(sm) + 1023) & ~1023u;
    const uint32_t sKV = sQ + 16384;

    const int tid = threadIdx.x, wid = tid >> 5, lid = tid & 31;
    const int qt = (int)gridDim.x - 1 - (int)blockIdx.x;
    const int bh = blockIdx.y;
    const int b = bh >> 4, h = bh & 15;
    const int qbase = qt * 128;
    const size_t tok0 = (size_t)b * SEQ;
    const size_t hoff = (size_t)h * 64;
    const int mw = wid * 16;

    {
        const int r = tid >> 1;
        const int half = tid & 1;
        const size_t g = (tok0 + qbase + r) * DM + hoff + half * 32;
#pragma unroll
        for (int i = 0; i < 4; i++) {
            uint32_t so = swz128(r * 128 + half * 64 + i * 16);
            cpasync16(sQ + so, Q + g + i * 8);
        }
    }

    const int njt = 2 * qt + 2;
    const int kr = tid >> 2;
    const int kq = tid & 3;
    const uint32_t kso0 = swz128(kr * 128 + kq * 32);
    const uint32_t kso1 = swz128(kr * 128 + kq * 32 + 16);

    auto issue_kv = [&](int jt) {
        const uint32_t st = sKV + (uint32_t)(jt % 3) * ATT_STAGEB;
        const size_t g = (tok0 + jt * 64 + kr) * DM + hoff + kq * 16;
        cpasync16(st +        kso0, K + g);
        cpasync16(st +        kso1, K + g + 8);
        cpasync16(st + 8192 + kso0, V + g);
        cpasync16(st + 8192 + kso1, V + g + 8);
    };

    issue_kv(0);
    asm volatile("cp.async.commit_group;");
    issue_kv(1);
    asm volatile("cp.async.commit_group;");

    float O[8][4];
#pragma unroll
    for (int j = 0; j < 8; j++)
#pragma unroll
        for (int e = 0; e < 4; e++) O[j][e] = 0.f;
    float m0 = -1e30f, m1 = -1e30f, l0 = 0.f, l1 = 0.f;

    const int rql = lid >> 2;
    const int cql = (lid & 3) * 2;
    const int row0g = qbase + mw + rql;
    const int row1g = row0g + 8;

    for (int jt = 0; jt < njt; jt++) {
        asm volatile("cp.async.wait_group 1;");
        __syncthreads();
        if (jt + 2 < njt) issue_kv(jt + 2);
        asm volatile("cp.async.commit_group;");

        const bool active = !(mw < 64 && jt == njt - 1);
        if (active) {
            const uint32_t stK = sKV + (uint32_t)(jt % 3) * ATT_STAGEB;
            const uint32_t stV = stK + 8192;

            float S[8][4];
#pragma unroll
            for (int j = 0; j < 8; j++)
#pragma unroll
                for (int e = 0; e < 4; e++) S[j][e] = 0.f;

#pragma unroll
            for (int ks = 0; ks < 4; ks++) {
                uint32_t q4[4];
                uint32_t qoff = swz128((mw + (lid & 15)) * 128 + ks * 32 + (lid >> 4) * 16);
                ldsm4(q4, sQ + qoff);
                uint32_t kf[8][2];
#pragma unroll
                for (int jj = 0; jj < 4; jj++) {
                    uint32_t koff = swz128((jj * 16 + (lid & 7) + ((lid >> 4) << 3)) * 128
                                           + ks * 32 + ((lid >> 3) & 1) * 16);
                    uint32_t t0[4];
                    ldsm4(t0, stK + koff);
                    kf[2*jj][0]=t0[0]; kf[2*jj][1]=t0[1];
                    kf[2*jj+1][0]=t0[2]; kf[2*jj+1][1]=t0[3];
                }
#pragma unroll
                for (int j = 0; j < 8; j++) mma16816(S[j], q4, kf[j][0], kf[j][1]);
            }

            const int colb = jt * 64;
            const bool diag = (jt >= 2 * qt);
#pragma unroll
            for (int j = 0; j < 8; j++)
#pragma unroll
                for (int e = 0; e < 4; e++) {
                    float v = S[j][e] * 0.125f;
                    if (diag) {
                        int col = colb + 8 * j + cql + (e & 1);
                        int row = (e < 2) ? row0g : row1g;
                        if (col > row) v = -1e30f;
                    }
                    S[j][e] = v;
                }

            float rm0 = -1e30f, rm1 = -1e30f;
#pragma unroll
            for (int j = 0; j < 8; j++) {
                rm0 = fmaxf(rm0, fmaxf(S[j][0], S[j][1]));
                rm1 = fmaxf(rm1, fmaxf(S[j][2], S[j][3]));
            }
            rm0 = fmaxf(rm0, __shfl_xor_sync(0xffffffffu, rm0, 1));
            rm0 = fmaxf(rm0, __shfl_xor_sync(0xffffffffu, rm0, 2));
            rm1 = fmaxf(rm1, __shfl_xor_sync(0xffffffffu, rm1, 1));
            rm1 = fmaxf(rm1, __shfl_xor_sync(0xffffffffu, rm1, 2));
            float mn0 = fmaxf(m0, rm0), mn1 = fmaxf(m1, rm1);
            float a0 = __expf(m0 - mn0), a1 = __expf(m1 - mn1);
            m0 = mn0; m1 = mn1;
            float rs0 = 0.f, rs1 = 0.f;
#pragma unroll
            for (int j = 0; j < 8; j++) {
                S[j][0] = __expf(S[j][0] - mn0);
                S[j][1] = __expf(S[j][1] - mn0);
                S[j][2] = __expf(S[j][2] - mn1);
                S[j][3] = __expf(S[j][3] - mn1);
                rs0 += S[j][0] + S[j][1];
                rs1 += S[j][2] + S[j][3];
            }
            rs0 += __shfl_xor_sync(0xffffffffu, rs0, 1);
            rs0 += __shfl_xor_sync(0xffffffffu, rs0, 2);
            rs1 += __shfl_xor_sync(0xffffffffu, rs1, 1);
            rs1 += __shfl_xor_sync(0xffffffffu, rs1, 2);
            l0 = l0 * a0 + rs0;
            l1 = l1 * a1 + rs1;
#pragma unroll
            for (int j = 0; j < 8; j++) {
                O[j][0] *= a0; O[j][1] *= a0; O[j][2] *= a1; O[j][3] *= a1;
            }

            uint32_t pa[4][4];
#pragma unroll
            for (int ks = 0; ks < 4; ks++) {
                pa[ks][0] = pack2(S[2*ks][0],   S[2*ks][1]);
                pa[ks][1] = pack2(S[2*ks][2],   S[2*ks][3]);
                pa[ks][2] = pack2(S[2*ks+1][0], S[2*ks+1][1]);
                pa[ks][3] = pack2(S[2*ks+1][2], S[2*ks+1][3]);
            }

#pragma unroll
            for (int ks = 0; ks < 4; ks++) {
                uint32_t vf[8][2];
                const int rowv = ks * 16 + ((lid >> 3) & 1) * 8 + (lid & 7);
                const int colv = (lid >> 4) * 16;
#pragma unroll
                for (int nb = 0; nb < 4; nb++) {
                    uint32_t voff = swz128(rowv * 128 + nb * 32 + colv);
                    uint32_t t0[4];
                    ldsm4t(t0, stV + voff);
                    vf[2*nb][0]=t0[0]; vf[2*nb][1]=t0[1];
                    vf[2*nb+1][0]=t0[2]; vf[2*nb+1][1]=t0[3];
                }
#pragma unroll
                for (int j = 0; j < 8; j++) mma16816(O[j], pa[ks], vf[j][0], vf[j][1]);
            }
        }
    }

    const float inv0 = 1.0f / l0, inv1 = 1.0f / l1;
    const size_t tq0 = (tok0 + row0g) * DM + hoff;
    const size_t tq1 = (tok0 + row1g) * DM + hoff;
#pragma unroll
    for (int j = 0; j < 8; j++) {
        const int c = 8 * j + cql;
        *(uint32_t*)&O_[tq0 + c] = pack2(O[j][0] * inv0, O[j][1] * inv0);
        *(uint32_t*)&O_[tq1 + c] = pack2(O[j][2] * inv1, O[j][3] * inv1);
    }
}

// =====================================================================
// conversions
// =====================================================================
__global__ __launch_bounds__(256)
void conv_act(const float* __restrict__ in, __half* __restrict__ hi)
{
    const size_t i = ((size_t)blockIdx.x * 256 + threadIdx.x) * 4;
    float4 v = *(const float4*)(in + i);
    *(uint32_t*)&hi[i]     = pack2(v.x, v.y);
    *(uint32_t*)&hi[i + 2] = pack2(v.z, v.w);
}

__global__ __launch_bounds__(256)
void conv_wT(const float* __restrict__ W, __half* __restrict__ hi, int K, int N)
{
    __shared__ float t[32][33];
    const int n0 = blockIdx.x * 32, k0 = blockIdx.y * 32;
    const int tx = threadIdx.x & 31, ty = threadIdx.x >> 5;
#pragma unroll
    for (int j = 0; j < 4; j++)
        t[ty + 8 * j][tx] = W[(size_t)(k0 + ty + 8 * j) * N + n0 + tx];
    __syncthreads();
#pragma unroll
    for (int j = 0; j < 4; j++) {
        size_t o = (size_t)(n0 + ty + 8 * j) * K + k0 + tx;
        hi[o] = __float2half_rn(t[tx][ty + 8 * j]);
    }
}

__global__ __launch_bounds__(256)
void conv_wT3(const float* __restrict__ W0, const float* __restrict__ W1,
              const float* __restrict__ W2, __half* __restrict__ hi)
{
    __shared__ float t[32][33];
    const int n0 = blockIdx.x * 32, k0 = blockIdx.y * 32;
    const int sel = n0 >> 10;
    const int nl = n0 & 1023;
    const float* W = (sel == 0) ? W0 : (sel == 1) ? W1 : W2;
    const int tx = threadIdx.x & 31, ty = threadIdx.x >> 5;
#pragma unroll
    for (int j = 0; j < 4; j++)
        t[ty + 8 * j][tx] = W[(size_t)(k0 + ty + 8 * j) * 1024 + nl + tx];
    __syncthreads();
#pragma unroll
    for (int j = 0; j < 4; j++) {
        size_t o = (size_t)(n0 + ty + 8 * j) * 1024 + k0 + tx;
        hi[o] = __float2half_rn(t[tx][ty + 8 * j]);
    }
}

__global__ void bias_cat(const float* __restrict__ b0, const float* __restrict__ b1,
                         const float* __restrict__ b2, float* __restrict__ out)
{
    int i = blockIdx.x * 256 + threadIdx.x;
    out[i] = (i < 1024) ? b0[i] : (i < 2048) ? b1[i - 1024] : b2[i - 2048];
}

// =====================================================================
// LayerNorm (+ optional fp16 out)
// =====================================================================
__global__ __launch_bounds__(256)
void ln_kernel(const float* __restrict__ in, const float* __restrict__ gamma,
               const float* __restrict__ beta, float* __restrict__ out,
               __half* __restrict__ oh)
{
    __shared__ float rs[8], rs2[8];
    const int row = blockIdx.x;
    const int t = threadIdx.x;
    float4 v = ((const float4*)(in + (size_t)row * DM))[t];
    float s  = v.x + v.y + v.z + v.w;
    float s2 = v.x * v.x + v.y * v.y + v.z * v.z + v.w * v.w;
#pragma unroll
    for (int off = 16; off; off >>= 1) {
        s  += __shfl_xor_sync(0xffffffffu, s, off);
        s2 += __shfl_xor_sync(0xffffffffu, s2, off);
    }
    if ((t & 31) == 0) { rs[t >> 5] = s; rs2[t >> 5] = s2; }
    __syncthreads();
    float ts = 0.f, ts2 = 0.f;
#pragma unroll
    for (int w = 0; w < 8; w++) { ts += rs[w]; ts2 += rs2[w]; }
    float mu   = ts * (1.0f / DM);
    float var  = ts2 * (1.0f / DM) - mu * mu;
    float rstd = rsqrtf(var + 1e-5f);
    float4 g4 = ((const float4*)gamma)[t];
    float4 b4 = ((const float4*)beta)[t];
    float4 o4;
    o4.x = (v.x - mu) * rstd * g4.x + b4.x;
    o4.y = (v.y - mu) * rstd * g4.y + b4.y;
    o4.z = (v.z - mu) * rstd * g4.z + b4.z;
    o4.w = (v.w - mu) * rstd * g4.w + b4.w;
    ((float4*)(out + (size_t)row * DM))[t] = o4;
    if (oh) {
        const size_t i = (size_t)row * DM + t * 4;
        *(uint32_t*)&oh[i]     = pack2(o4.x, o4.y);
        *(uint32_t*)&oh[i + 2] = pack2(o4.z, o4.w);
    }
}

// =====================================================================
extern "C" void kernel_launch(void* const* d_in, const int* in_sizes, int n_in,
                              void* d_out, int out_size)
{
    (void)in_sizes; (void)n_in; (void)out_size;
    const float* x   = (const float*)d_in[0];
    const float* Wq  = (const float*)d_in[1];
    const float* bq  = (const float*)d_in[2];
    const float* Wk  = (const float*)d_in[3];
    const float* bk  = (const float*)d_in[4];
    const float* Wv  = (const float*)d_in[5];
    const float* bv  = (const float*)d_in[6];
    const float* Wo  = (const float*)d_in[7];
    const float* bo  = (const float*)d_in[8];
    const float* W1  = (const float*)d_in[9];
    const float* b1  = (const float*)d_in[10];
    const float* W2  = (const float*)d_in[11];
    const float* b2  = (const float*)d_in[12];
    const float* g1  = (const float*)d_in[13];
    const float* be1 = (const float*)d_in[14];
    const float* g2  = (const float*)d_in[15];
    const float* be2 = (const float*)d_in[16];
    float* out = (float*)d_out;

    float *gt0, *gx1, *gbqkv;
    cudaGetSymbolAddress((void**)&gt0, g_t0);
    cudaGetSymbolAddress((void**)&gx1, g_x1);
    cudaGetSymbolAddress((void**)&gbqkv, g_bqkv);

    __half *xh, *qh, *kh, *vh, *ctxh, *x1h, *ffh;
    __half *wqkvh, *woh, *w1h, *w2h;
    cudaGetSymbolAddress((void**)&xh,    g_xh);
    cudaGetSymbolAddress((void**)&qh,    g_qh);
    cudaGetSymbolAddress((void**)&kh,    g_kh);
    cudaGetSymbolAddress((void**)&vh,    g_vh);
    cudaGetSymbolAddress((void**)&ctxh,  g_ctxh);
    cudaGetSymbolAddress((void**)&x1h,   g_x1h);
    cudaGetSymbolAddress((void**)&ffh,   g_ffh);
    cudaGetSymbolAddress((void**)&wqkvh, g_wqkvh);
    cudaGetSymbolAddress((void**)&woh,   g_woh);
    cudaGetSymbolAddress((void**)&w1h,   g_w1h);
    cudaGetSymbolAddress((void**)&w2h,   g_w2h);

    cudaFuncSetAttribute(mma_gemm, cudaFuncAttributeMaxDynamicSharedMemorySize, SMEM_MMA);
    cudaFuncSetAttribute(attn_mma, cudaFuncAttributeMaxDynamicSharedMemorySize, SMEM_ATT);

    // ---- weight prep (fp16) ----
    conv_wT3<<<dim3(3 * DM / 32, DM / 32), 256>>>(Wq, Wk, Wv, wqkvh);
    conv_wT<<<dim3(DM / 32,  DM / 32),  256>>>(Wo, woh, DM, DM);
    conv_wT<<<dim3(DFF / 32, DM / 32),  256>>>(W1, w1h, DM, DFF);
    conv_wT<<<dim3(DM / 32,  DFF / 32), 256>>>(W2, w2h, DFF, DM);
    bias_cat<<<12, 256>>>(bq, bk, bv, gbqkv);

    // ---- x convert ----
    conv_act<<<(NTOK * DM) / 1024, 256>>>(x, xh);

    // ---- fused QKV GEMM (N=3072) ----
    mma_gemm<<<dim3(3 * DM / 128, NTOK / 128), 256, SMEM_MMA>>>(
        xh, wqkvh, gbqkv, nullptr, nullptr,
        qh, kh, vh, NTOK, 3 * DM, DM, DM, 0, 1);

    // ---- attention ----
    attn_mma<<<dim3(SEQ / 128, 32), 256, SMEM_ATT>>>(qh, kh, vh, ctxh);

    // ---- Wo + residual, LN1 (+fp16) ----
    mma_gemm<<<dim3(DM / 128, NTOK / 128), 256, SMEM_MMA>>>(
        ctxh, woh, bo, x, gt0,
        nullptr, nullptr, nullptr, NTOK, DM, DM, DM, 2, 0);
    ln_kernel<<<NTOK, 256>>>(gt0, g1, be1, gx1, x1h);

    // ---- FFN ----
    mma_gemm<<<dim3(DFF / 128, NTOK / 128), 256, SMEM_MMA>>>(
        x1h, w1h, b1, nullptr, nullptr,
        ffh, nullptr, nullptr, NTOK, DFF, DM, DFF, 1, 0);
    mma_gemm<<<dim3(DM / 128, NTOK / 128), 256, SMEM_MMA>>>(
        ffh, w2h, b2, gx1, gt0,
        nullptr, nullptr, nullptr, NTOK, DM, DFF, DM, 2, 0);
    ln_kernel<<<NTOK, 256>>>(gt0, g2, be2, out, nullptr);
}

// round 14
// speedup vs baseline: 2.3568x; 1.0793x over previous
#include <cuda_runtime.h>
#include <cuda_fp16.h>
#include <cstdint>

#define NTOK 4096   // B*L
#define DM   1024
#define DFF  4096
#define SEQ  2048

// ---------------- scratch (device globals: allocation-free) ----------------
__device__ float g_t0[NTOK * DM];
__device__ float g_x1[NTOK * DM];

__device__ __half g_xh[NTOK * DM];
__device__ __half g_qh[NTOK * DM];
__device__ __half g_kh[NTOK * DM];
__device__ __half g_vh[NTOK * DM];
__device__ __half g_ctxh[NTOK * DM];
__device__ __half g_x1h[NTOK * DM];
__device__ __half g_ffh[(size_t)NTOK * DFF];
__device__ __half g_wqkvh[3 * DM * DM];
__device__ float g_bqkv[3 * DM];
__device__ __half g_woh[DM * DM];
__device__ __half g_w1h[(size_t)DFF * DM];
__device__ __half g_w2h[(size_t)DM * DFF];

// ---------------- PTX helpers (family-portable; NO tcgen05) ----------------
__device__ __forceinline__ uint32_t smem_u32(const void* p) {
    uint32_t a;
    asm("{ .reg .u64 t; cvta.to.shared.u64 t, %1; cvt.u32.u64 %0, t; }" : "=r"(a) : "l"(p));
    return a;
}
__device__ __forceinline__ void cpasync16(uint32_t dst, const void* src) {
    asm volatile("cp.async.cg.shared.global [%0], [%1], 16;" :: "r"(dst), "l"(src));
}
__device__ __forceinline__ void ldsm4(uint32_t (&r)[4], uint32_t addr) {
    asm volatile("ldmatrix.sync.aligned.m8n8.x4.shared.b16 {%0,%1,%2,%3}, [%4];"
        : "=r"(r[0]), "=r"(r[1]), "=r"(r[2]), "=r"(r[3]) : "r"(addr));
}
__device__ __forceinline__ void ldsm4t(uint32_t (&r)[4], uint32_t addr) {
    asm volatile("ldmatrix.sync.aligned.m8n8.x4.trans.shared.b16 {%0,%1,%2,%3}, [%4];"
        : "=r"(r[0]), "=r"(r[1]), "=r"(r[2]), "=r"(r[3]) : "r"(addr));
}
__device__ __forceinline__ void mma16816(float (&c)[4], const uint32_t (&a)[4],
                                         uint32_t b0, uint32_t b1) {
    asm volatile("mma.sync.aligned.m16n8k16.row.col.f32.f16.f16.f32 "
        "{%0,%1,%2,%3}, {%4,%5,%6,%7}, {%8,%9}, {%0,%1,%2,%3};"
        : "+f"(c[0]), "+f"(c[1]), "+f"(c[2]), "+f"(c[3])
        : "r"(a[0]), "r"(a[1]), "r"(a[2]), "r"(a[3]), "r"(b0), "r"(b1));
}
__device__ __forceinline__ uint32_t h2u(__half2 v) {
    return *reinterpret_cast<uint32_t*>(&v);
}
__device__ __forceinline__ uint32_t pack2(float a, float b) {
    __half2 h = __floats2half2_rn(a, b);
    return h2u(h);
}
__device__ __forceinline__ uint32_t swz128(uint32_t off) { return off ^ ((off >> 3) & 0x70); }

// =====================================================================
// mma_gemm: C = A[M,K] @ B[N,K]^T + bias   (fp16 in, fp32 accum)
// CTA tile 256x128, warp tile 64x64 (4m x 2n warps), BK=64, 3-stage
// cp.async pipeline, 1 MMA pass. epi: 0=none, 1=GELU, 2=+res.
// fused!=0: N=3072 QKV routing per 1024-col block.
// =====================================================================
#define ATILEB 32768                  // 256 rows x 128 B
#define BTILEB 16384                  // 128 rows x 128 B
#define GSTAGEB (ATILEB + BTILEB)     // 48 KB
#define SMEM_MMA (3 * GSTAGEB + 1024)

__global__ __launch_bounds__(256, 1)
void mma_gemm(const __half* __restrict__ A, const __half* __restrict__ B,
              const float* __restrict__ bias, const float* __restrict__ res,
              float* __restrict__ Cf,
              __half* __restrict__ Ch0, __half* __restrict__ Ch1,
              __half* __restrict__ Ch2,
              int M, int N, int K, int outN, int epi, int fused)
{
    extern __shared__ char smem[];
    const uint32_t s0 = (smem_u32(smem) + 1023) & ~1023u;

    const int tid = threadIdx.x;
    const int wid = tid >> 5, lid = tid & 31;
    const int brow = blockIdx.y << 8, bcol = blockIdx.x << 7;
    const int mw = (wid & 3) << 6;     // 4 m-warps x 64 rows
    const int nw = (wid >> 2) << 6;    // 2 n-warps x 64 cols

    // loader mapping
    // A: 512 half-rows (row = slot>>1, half = slot&1), slots tid and tid+256
    // B: 256 half-rows, slot = tid
    const int ar0 = tid >> 1, ah0 = tid & 1;
    const int ar1 = (tid + 256) >> 1, ah1 = tid & 1;
    const int br = tid >> 1, bhh = tid & 1;
    uint32_t swA0[4], swA1[4], swB[4];
#pragma unroll
    for (int i = 0; i < 4; i++) {
        swA0[i] = swz128(ar0 * 128 + ah0 * 64 + i * 16);
        swA1[i] = swz128(ar1 * 128 + ah1 * 64 + i * 16);
        swB[i]  = swz128(br * 128 + bhh * 64 + i * 16);
    }
    const size_t ga0 = (size_t)(brow + ar0) * K + ah0 * 32;
    const size_t ga1 = (size_t)(brow + ar1) * K + ah1 * 32;
    const size_t gb  = (size_t)(bcol + br)  * K + bhh * 32;

    const int nchunk = K >> 6;

    auto issue = [&](int c) {
        const uint32_t st = s0 + (uint32_t)(c % 3) * GSTAGEB;
        const size_t k0 = (size_t)c << 6;
#pragma unroll
        for (int i = 0; i < 4; i++) {
            cpasync16(st +          swA0[i], A + ga0 + k0 + i * 8);
            cpasync16(st +          swA1[i], A + ga1 + k0 + i * 8);
            cpasync16(st + ATILEB + swB[i],  B + gb  + k0 + i * 8);
        }
    };

    issue(0);
    asm volatile("cp.async.commit_group;");
    issue(1);
    asm volatile("cp.async.commit_group;");

    float acc[4][8][4];
#pragma unroll
    for (int i = 0; i < 4; i++)
#pragma unroll
        for (int j = 0; j < 8; j++)
#pragma unroll
            for (int t = 0; t < 4; t++) acc[i][j][t] = 0.f;

    const int a_row = lid & 15;
    const int a_h   = (lid >> 4) * 16;
    const int b_row = (lid & 7) + ((lid >> 4) << 3);
    const int b_h   = ((lid >> 3) & 1) * 16;

    for (int c = 0; c < nchunk; c++) {
        asm volatile("cp.async.wait_group 1;");
        __syncthreads();
        if (c + 2 < nchunk) issue(c + 2);
        asm volatile("cp.async.commit_group;");

        const uint32_t st = s0 + (uint32_t)(c % 3) * GSTAGEB;
        const uint32_t sA = st, sB = st + ATILEB;

#pragma unroll
        for (int ks = 0; ks < 4; ks++) {
            uint32_t af[4][4];
#pragma unroll
            for (int i = 0; i < 4; i++) {
                uint32_t off = swz128((mw + i * 16 + a_row) * 128 + ks * 32 + a_h);
                ldsm4(af[i], sA + off);
            }
            uint32_t bf[8][2];
#pragma unroll
            for (int jj = 0; jj < 4; jj++) {
                uint32_t off = swz128((nw + jj * 16 + b_row) * 128 + ks * 32 + b_h);
                uint32_t t0[4];
                ldsm4(t0, sB + off);
                bf[2*jj][0] = t0[0]; bf[2*jj][1] = t0[1];
                bf[2*jj+1][0] = t0[2]; bf[2*jj+1][1] = t0[3];
            }
#pragma unroll
            for (int i = 0; i < 4; i++)
#pragma unroll
                for (int j = 0; j < 8; j++)
                    mma16816(acc[i][j], af[i], bf[j][0], bf[j][1]);
        }
    }

    // ---- epilogue ----
    int sel = fused ? (bcol >> 10) : 0;
    const int nbase = fused ? (bcol & 1023) : bcol;
    __half* Ch = (sel == 0) ? Ch0 : (sel == 1) ? Ch1 : Ch2;

    const int erow = lid >> 2;
    const int ecol = (lid & 3) << 1;
#pragma unroll
    for (int i = 0; i < 4; i++)
#pragma unroll
        for (int j = 0; j < 8; j++)
#pragma unroll
            for (int h = 0; h < 2; h++) {
                const int m = brow + mw + i * 16 + erow + h * 8;
                const int ng = bcol + nw + j * 8 + ecol;
                const int nl = nbase + nw + j * 8 + ecol;
                float v0 = acc[i][j][h * 2 + 0] + bias[ng];
                float v1 = acc[i][j][h * 2 + 1] + bias[ng + 1];
                const size_t off = (size_t)m * outN + nl;
                if (epi == 1) {
                    v0 = 0.5f * v0 * (1.0f + erff(v0 * 0.70710678118654752f));
                    v1 = 0.5f * v1 * (1.0f + erff(v1 * 0.70710678118654752f));
                } else if (epi == 2) {
                    float2 rr = *(const float2*)&res[off];
                    v0 += rr.x; v1 += rr.y;
                }
                if (Cf) *(float2*)&Cf[off] = make_float2(v0, v1);
                if (Ch) *(uint32_t*)&Ch[off] = pack2(v0, v1);
            }
}

// =====================================================================
// Causal flash attention, pure fp16 HMMA, fp32 softmax/accumulators.
// =====================================================================
#define ATT_STAGEB 16384              // K 8K + V 8K per stage
#define SMEM_ATT (1024 + 16384 + 3 * ATT_STAGEB)

__global__ __launch_bounds__(256, 2)
void attn_mma(const __half* __restrict__ Q, const __half* __restrict__ K,
              const __half* __restrict__ V, __half* __restrict__ O_)
{
    extern __shared__ char sm[];
    const uint32_t sQ  = (smem_u32(sm) + 1023) & ~1023u;
    const uint32_t sKV = sQ + 16384;

    const int tid = threadIdx.x, wid = tid >> 5, lid = tid & 31;
    const int qt = (int)gridDim.x - 1 - (int)blockIdx.x;
    const int bh = blockIdx.y;
    const int b = bh >> 4, h = bh & 15;
    const int qbase = qt * 128;
    const size_t tok0 = (size_t)b * SEQ;
    const size_t hoff = (size_t)h * 64;
    const int mw = wid * 16;

    {
        const int r = tid >> 1;
        const int half = tid & 1;
        const size_t g = (tok0 + qbase + r) * DM + hoff + half * 32;
#pragma unroll
        for (int i = 0; i < 4; i++) {
            uint32_t so = swz128(r * 128 + half * 64 + i * 16);
            cpasync16(sQ + so, Q + g + i * 8);
        }
    }

    const int njt = 2 * qt + 2;
    const int kr = tid >> 2;
    const int kq = tid & 3;
    const uint32_t kso0 = swz128(kr * 128 + kq * 32);
    const uint32_t kso1 = swz128(kr * 128 + kq * 32 + 16);

    auto issue_kv = [&](int jt) {
        const uint32_t st = sKV + (uint32_t)(jt % 3) * ATT_STAGEB;
        const size_t g = (tok0 + jt * 64 + kr) * DM + hoff + kq * 16;
        cpasync16(st +        kso0, K + g);
        cpasync16(st +        kso1, K + g + 8);
        cpasync16(st + 8192 + kso0, V + g);
        cpasync16(st + 8192 + kso1, V + g + 8);
    };

    issue_kv(0);
    asm volatile("cp.async.commit_group;");
    issue_kv(1);
    asm volatile("cp.async.commit_group;");

    float O[8][4];
#pragma unroll
    for (int j = 0; j < 8; j++)
#pragma unroll
        for (int e = 0; e < 4; e++) O[j][e] = 0.f;
    float m0 = -1e30f, m1 = -1e30f, l0 = 0.f, l1 = 0.f;

    const int rql = lid >> 2;
    const int cql = (lid & 3) * 2;
    const int row0g = qbase + mw + rql;
    const int row1g = row0g + 8;

    for (int jt = 0; jt < njt; jt++) {
        asm volatile("cp.async.wait_group 1;");
        __syncthreads();
        if (jt + 2 < njt) issue_kv(jt + 2);
        asm volatile("cp.async.commit_group;");

        const bool active = !(mw < 64 && jt == njt - 1);
        if (active) {
            const uint32_t stK = sKV + (uint32_t)(jt % 3) * ATT_STAGEB;
            const uint32_t stV = stK + 8192;

            float S[8][4];
#pragma unroll
            for (int j = 0; j < 8; j++)
#pragma unroll
                for (int e = 0; e < 4; e++) S[j][e] = 0.f;

#pragma unroll
            for (int ks = 0; ks < 4; ks++) {
                uint32_t q4[4];
                uint32_t qoff = swz128((mw + (lid & 15)) * 128 + ks * 32 + (lid >> 4) * 16);
                ldsm4(q4, sQ + qoff);
                uint32_t kf[8][2];
#pragma unroll
                for (int jj = 0; jj < 4; jj++) {
                    uint32_t koff = swz128((jj * 16 + (lid & 7) + ((lid >> 4) << 3)) * 128
                                           + ks * 32 + ((lid >> 3) & 1) * 16);
                    uint32_t t0[4];
                    ldsm4(t0, stK + koff);
                    kf[2*jj][0]=t0[0]; kf[2*jj][1]=t0[1];
                    kf[2*jj+1][0]=t0[2]; kf[2*jj+1][1]=t0[3];
                }
#pragma unroll
                for (int j = 0; j < 8; j++) mma16816(S[j], q4, kf[j][0], kf[j][1]);
            }

            const int colb = jt * 64;
            const bool diag = (jt >= 2 * qt);
#pragma unroll
            for (int j = 0; j < 8; j++)
#pragma unroll
                for (int e = 0; e < 4; e++) {
                    float v = S[j][e] * 0.125f;
                    if (diag) {
                        int col = colb + 8 * j + cql + (e & 1);
                        int row = (e < 2) ? row0g : row1g;
                        if (col > row) v = -1e30f;
                    }
                    S[j][e] = v;
                }

            float rm0 = -1e30f, rm1 = -1e30f;
#pragma unroll
            for (int j = 0; j < 8; j++) {
                rm0 = fmaxf(rm0, fmaxf(S[j][0], S[j][1]));
                rm1 = fmaxf(rm1, fmaxf(S[j][2], S[j][3]));
            }
            rm0 = fmaxf(rm0, __shfl_xor_sync(0xffffffffu, rm0, 1));
            rm0 = fmaxf(rm0, __shfl_xor_sync(0xffffffffu, rm0, 2));
            rm1 = fmaxf(rm1, __shfl_xor_sync(0xffffffffu, rm1, 1));
            rm1 = fmaxf(rm1, __shfl_xor_sync(0xffffffffu, rm1, 2));
            float mn0 = fmaxf(m0, rm0), mn1 = fmaxf(m1, rm1);
            float a0 = __expf(m0 - mn0), a1 = __expf(m1 - mn1);
            m0 = mn0; m1 = mn1;
            float rs0 = 0.f, rs1 = 0.f;
#pragma unroll
            for (int j = 0; j < 8; j++) {
                S[j][0] = __expf(S[j][0] - mn0);
                S[j][1] = __expf(S[j][1] - mn0);
                S[j][2] = __expf(S[j][2] - mn1);
                S[j][3] = __expf(S[j][3] - mn1);
                rs0 += S[j][0] + S[j][1];
                rs1 += S[j][2] + S[j][3];
            }
            rs0 += __shfl_xor_sync(0xffffffffu, rs0, 1);
            rs0 += __shfl_xor_sync(0xffffffffu, rs0, 2);
            rs1 += __shfl_xor_sync(0xffffffffu, rs1, 1);
            rs1 += __shfl_xor_sync(0xffffffffu, rs1, 2);
            l0 = l0 * a0 + rs0;
            l1 = l1 * a1 + rs1;
#pragma unroll
            for (int j = 0; j < 8; j++) {
                O[j][0] *= a0; O[j][1] *= a0; O[j][2] *= a1; O[j][3] *= a1;
            }

            uint32_t pa[4][4];
#pragma unroll
            for (int ks = 0; ks < 4; ks++) {
                pa[ks][0] = pack2(S[2*ks][0],   S[2*ks][1]);
                pa[ks][1] = pack2(S[2*ks][2],   S[2*ks][3]);
                pa[ks][2] = pack2(S[2*ks+1][0], S[2*ks+1][1]);
                pa[ks][3] = pack2(S[2*ks+1][2], S[2*ks+1][3]);
            }

#pragma unroll
            for (int ks = 0; ks < 4; ks++) {
                uint32_t vf[8][2];
                const int rowv = ks * 16 + ((lid >> 3) & 1) * 8 + (lid & 7);
                const int colv = (lid >> 4) * 16;
#pragma unroll
                for (int nb = 0; nb < 4; nb++) {
                    uint32_t voff = swz128(rowv * 128 + nb * 32 + colv);
                    uint32_t t0[4];
                    ldsm4t(t0, stV + voff);
                    vf[2*nb][0]=t0[0]; vf[2*nb][1]=t0[1];
                    vf[2*nb+1][0]=t0[2]; vf[2*nb+1][1]=t0[3];
                }
#pragma unroll
                for (int j = 0; j < 8; j++) mma16816(O[j], pa[ks], vf[j][0], vf[j][1]);
            }
        }
    }

    const float inv0 = 1.0f / l0, inv1 = 1.0f / l1;
    const size_t tq0 = (tok0 + row0g) * DM + hoff;
    const size_t tq1 = (tok0 + row1g) * DM + hoff;
#pragma unroll
    for (int j = 0; j < 8; j++) {
        const int c = 8 * j + cql;
        *(uint32_t*)&O_[tq0 + c] = pack2(O[j][0] * inv0, O[j][1] * inv0);
        *(uint32_t*)&O_[tq1 + c] = pack2(O[j][2] * inv1, O[j][3] * inv1);
    }
}

// =====================================================================
// conversions
// =====================================================================
__global__ __launch_bounds__(256)
void conv_act(const float* __restrict__ in, __half* __restrict__ hi)
{
    const size_t i = ((size_t)blockIdx.x * 256 + threadIdx.x) * 4;
    float4 v = *(const float4*)(in + i);
    *(uint32_t*)&hi[i]     = pack2(v.x, v.y);
    *(uint32_t*)&hi[i + 2] = pack2(v.z, v.w);
}

__global__ __launch_bounds__(256)
void conv_wT(const float* __restrict__ W, __half* __restrict__ hi, int K, int N)
{
    __shared__ float t[32][33];
    const int n0 = blockIdx.x * 32, k0 = blockIdx.y * 32;
    const int tx = threadIdx.x & 31, ty = threadIdx.x >> 5;
#pragma unroll
    for (int j = 0; j < 4; j++)
        t[ty + 8 * j][tx] = W[(size_t)(k0 + ty + 8 * j) * N + n0 + tx];
    __syncthreads();
#pragma unroll
    for (int j = 0; j < 4; j++) {
        size_t o = (size_t)(n0 + ty + 8 * j) * K + k0 + tx;
        hi[o] = __float2half_rn(t[tx][ty + 8 * j]);
    }
}

__global__ __launch_bounds__(256)
void conv_wT3(const float* __restrict__ W0, const float* __restrict__ W1,
              const float* __restrict__ W2, __half* __restrict__ hi)
{
    __shared__ float t[32][33];
    const int n0 = blockIdx.x * 32, k0 = blockIdx.y * 32;
    const int sel = n0 >> 10;
    const int nl = n0 & 1023;
    const float* W = (sel == 0) ? W0 : (sel == 1) ? W1 : W2;
    const int tx = threadIdx.x & 31, ty = threadIdx.x >> 5;
#pragma unroll
    for (int j = 0; j < 4; j++)
        t[ty + 8 * j][tx] = W[(size_t)(k0 + ty + 8 * j) * 1024 + nl + tx];
    __syncthreads();
#pragma unroll
    for (int j = 0; j < 4; j++) {
        size_t o = (size_t)(n0 + ty + 8 * j) * 1024 + k0 + tx;
        hi[o] = __float2half_rn(t[tx][ty + 8 * j]);
    }
}

__global__ void bias_cat(const float* __restrict__ b0, const float* __restrict__ b1,
                         const float* __restrict__ b2, float* __restrict__ out)
{
    int i = blockIdx.x * 256 + threadIdx.x;
    out[i] = (i < 1024) ? b0[i] : (i < 2048) ? b1[i - 1024] : b2[i - 2048];
}

// =====================================================================
// LayerNorm (+ optional fp16 out)
// =====================================================================
__global__ __launch_bounds__(256)
void ln_kernel(const float* __restrict__ in, const float* __restrict__ gamma,
               const float* __restrict__ beta, float* __restrict__ out,
               __half* __restrict__ oh)
{
    __shared__ float rs[8], rs2[8];
    const int row = blockIdx.x;
    const int t = threadIdx.x;
    float4 v = ((const float4*)(in + (size_t)row * DM))[t];
    float s  = v.x + v.y + v.z + v.w;
    float s2 = v.x * v.x + v.y * v.y + v.z * v.z + v.w * v.w;
#pragma unroll
    for (int off = 16; off; off >>= 1) {
        s  += __shfl_xor_sync(0xffffffffu, s, off);
        s2 += __shfl_xor_sync(0xffffffffu, s2, off);
    }
    if ((t & 31) == 0) { rs[t >> 5] = s; rs2[t >> 5] = s2; }
    __syncthreads();
    float ts = 0.f, ts2 = 0.f;
#pragma unroll
    for (int w = 0; w < 8; w++) { ts += rs[w]; ts2 += rs2[w]; }
    float mu   = ts * (1.0f / DM);
    float var  = ts2 * (1.0f / DM) - mu * mu;
    float rstd = rsqrtf(var + 1e-5f);
    float4 g4 = ((const float4*)gamma)[t];
    float4 b4 = ((const float4*)beta)[t];
    float4 o4;
    o4.x = (v.x - mu) * rstd * g4.x + b4.x;
    o4.y = (v.y - mu) * rstd * g4.y + b4.y;
    o4.z = (v.z - mu) * rstd * g4.z + b4.z;
    o4.w = (v.w - mu) * rstd * g4.w + b4.w;
    ((float4*)(out + (size_t)row * DM))[t] = o4;
    if (oh) {
        const size_t i = (size_t)row * DM + t * 4;
        *(uint32_t*)&oh[i]     = pack2(o4.x, o4.y);
        *(uint32_t*)&oh[i + 2] = pack2(o4.z, o4.w);
    }
}

// =====================================================================
extern "C" void kernel_launch(void* const* d_in, const int* in_sizes, int n_in,
                              void* d_out, int out_size)
{
    (void)in_sizes; (void)n_in; (void)out_size;
    const float* x   = (const float*)d_in[0];
    const float* Wq  = (const float*)d_in[1];
    const float* bq  = (const float*)d_in[2];
    const float* Wk  = (const float*)d_in[3];
    const float* bk  = (const float*)d_in[4];
    const float* Wv  = (const float*)d_in[5];
    const float* bv  = (const float*)d_in[6];
    const float* Wo  = (const float*)d_in[7];
    const float* bo  = (const float*)d_in[8];
    const float* W1  = (const float*)d_in[9];
    const float* b1  = (const float*)d_in[10];
    const float* W2  = (const float*)d_in[11];
    const float* b2  = (const float*)d_in[12];
    const float* g1  = (const float*)d_in[13];
    const float* be1 = (const float*)d_in[14];
    const float* g2  = (const float*)d_in[15];
    const float* be2 = (const float*)d_in[16];
    float* out = (float*)d_out;

    float *gt0, *gx1, *gbqkv;
    cudaGetSymbolAddress((void**)&gt0, g_t0);
    cudaGetSymbolAddress((void**)&gx1, g_x1);
    cudaGetSymbolAddress((void**)&gbqkv, g_bqkv);

    __half *xh, *qh, *kh, *vh, *ctxh, *x1h, *ffh;
    __half *wqkvh, *woh, *w1h, *w2h;
    cudaGetSymbolAddress((void**)&xh,    g_xh);
    cudaGetSymbolAddress((void**)&qh,    g_qh);
    cudaGetSymbolAddress((void**)&kh,    g_kh);
    cudaGetSymbolAddress((void**)&vh,    g_vh);
    cudaGetSymbolAddress((void**)&ctxh,  g_ctxh);
    cudaGetSymbolAddress((void**)&x1h,   g_x1h);
    cudaGetSymbolAddress((void**)&ffh,   g_ffh);
    cudaGetSymbolAddress((void**)&wqkvh, g_wqkvh);
    cudaGetSymbolAddress((void**)&woh,   g_woh);
    cudaGetSymbolAddress((void**)&w1h,   g_w1h);
    cudaGetSymbolAddress((void**)&w2h,   g_w2h);

    cudaFuncSetAttribute(mma_gemm, cudaFuncAttributeMaxDynamicSharedMemorySize, SMEM_MMA);
    cudaFuncSetAttribute(attn_mma, cudaFuncAttributeMaxDynamicSharedMemorySize, SMEM_ATT);

    // one-time side-stream for weight prep (host resources, no device mem)
    static cudaStream_t s2 = nullptr;
    static cudaEvent_t evFork = nullptr, evJoin = nullptr;
    if (!s2) {
        cudaStreamCreateWithFlags(&s2, cudaStreamNonBlocking);
        cudaEventCreateWithFlags(&evFork, cudaEventDisableTiming);
        cudaEventCreateWithFlags(&evJoin, cudaEventDisableTiming);
    }

    // ---- critical-path prep: QKV weights + bias + x convert ----
    conv_wT3<<<dim3(3 * DM / 32, DM / 32), 256>>>(Wq, Wk, Wv, wqkvh);
    bias_cat<<<12, 256>>>(bq, bk, bv, gbqkv);
    conv_act<<<(NTOK * DM) / 1024, 256>>>(x, xh);

    // ---- fork: Wo/W1/W2 prep runs concurrent with QKV GEMM + attention ----
    cudaEventRecord(evFork, 0);
    cudaStreamWaitEvent(s2, evFork, 0);
    conv_wT<<<dim3(DM / 32,  DM / 32),  256, 0, s2>>>(Wo, woh, DM, DM);
    conv_wT<<<dim3(DFF / 32, DM / 32),  256, 0, s2>>>(W1, w1h, DM, DFF);
    conv_wT<<<dim3(DM / 32,  DFF / 32), 256, 0, s2>>>(W2, w2h, DFF, DM);
    cudaEventRecord(evJoin, s2);

    // ---- fused QKV GEMM (N=3072) ----
    mma_gemm<<<dim3(3 * DM / 128, NTOK / 256), 256, SMEM_MMA>>>(
        xh, wqkvh, gbqkv, nullptr, nullptr,
        qh, kh, vh, NTOK, 3 * DM, DM, DM, 0, 1);

    // ---- attention ----
    attn_mma<<<dim3(SEQ / 128, 32), 256, SMEM_ATT>>>(qh, kh, vh, ctxh);

    // ---- join prep stream; Wo + residual, LN1 (+fp16) ----
    cudaStreamWaitEvent(0, evJoin, 0);
    mma_gemm<<<dim3(DM / 128, NTOK / 256), 256, SMEM_MMA>>>(
        ctxh, woh, bo, x, gt0,
        nullptr, nullptr, nullptr, NTOK, DM, DM, DM, 2, 0);
    ln_kernel<<<NTOK, 256>>>(gt0, g1, be1, gx1, x1h);

    // ---- FFN ----
    mma_gemm<<<dim3(DFF / 128, NTOK / 256), 256, SMEM_MMA>>>(
        x1h, w1h, b1, nullptr, nullptr,
        ffh, nullptr, nullptr, NTOK, DFF, DM, DFF, 1, 0);
    mma_gemm<<<dim3(DM / 128, NTOK / 256), 256, SMEM_MMA>>>(
        ffh, w2h, b2, gx1, gt0,
        nullptr, nullptr, nullptr, NTOK, DM, DFF, DM, 2, 0);
    ln_kernel<<<NTOK, 256>>>(gt0, g2, be2, out, nullptr);
}